// round 1
// baseline (speedup 1.0000x reference)
#include <cuda_runtime.h>
#include <cstdint>

#define NTHREADS 256

// Transposed W_tree: g_WT[h][e] = W_tree[e][h], h in [0,256), e in [0,128)
__device__ float g_WT[256 * 128];
// 1 if tokens buffer is int64, 0 if int32 (JAX may downcast silently)
__device__ int g_tok_is64;

__global__ void prep_kernel(const float* __restrict__ W, const int* __restrict__ tok32) {
    int i = blockIdx.x * 256 + threadIdx.x;
    if (i < 128 * 256) {
        int e = i >> 8;
        int h = i & 255;
        g_WT[h * 128 + e] = W[i];
    }
    if (blockIdx.x == 0 && threadIdx.x == 0) {
        // int64 little-endian values < 2^31: odd int32 words are all zero.
        int is64 = 1;
        for (int k = 1; k < 256; k += 2) {
            if (tok32[k] != 0) { is64 = 0; break; }
        }
        g_tok_is64 = is64;
    }
}

template <int R>
__device__ __forceinline__ void compute_group(
    const float* __restrict__ reps,
    const float4* __restrict__ WT4,
    const float4* __restrict__ b4p,
    int n0, int lane, float4* out)
{
    float4 b4 = b4p[lane];
    float4 acc[R];
#pragma unroll
    for (int r = 0; r < R; ++r) acc[r] = b4;
    const float4* c4[R];
#pragma unroll
    for (int r = 0; r < R; ++r)
        c4[r] = reinterpret_cast<const float4*>(reps + (n0 + r) * 256);

#pragma unroll 4
    for (int h4 = 0; h4 < 64; ++h4) {
        // Row h of W_T: 128 floats; lane takes e = 4*lane..4*lane+3 -> conflict-free LDS.128
        float4 w0 = WT4[(h4 * 4 + 0) * 32 + lane];
        float4 w1 = WT4[(h4 * 4 + 1) * 32 + lane];
        float4 w2 = WT4[(h4 * 4 + 2) * 32 + lane];
        float4 w3 = WT4[(h4 * 4 + 3) * 32 + lane];
#pragma unroll
        for (int r = 0; r < R; ++r) {
            float4 c = c4[r][h4];  // broadcast load (all lanes same address)
            acc[r].x += c.x * w0.x + c.y * w1.x + c.z * w2.x + c.w * w3.x;
            acc[r].y += c.x * w0.y + c.y * w1.y + c.z * w2.y + c.w * w3.y;
            acc[r].z += c.x * w0.z + c.y * w1.z + c.z * w2.z + c.w * w3.z;
            acc[r].w += c.x * w0.w + c.y * w1.w + c.z * w2.w + c.w * w3.w;
        }
    }
#pragma unroll
    for (int r = 0; r < R; ++r) {
        out[r].x = tanhf(acc[r].x);
        out[r].y = tanhf(acc[r].y);
        out[r].z = tanhf(acc[r].z);
        out[r].w = tanhf(acc[r].w);
    }
}

__global__ __launch_bounds__(NTHREADS, 1)
void tree_kernel(const void* __restrict__ tokens_raw,
                 const float* __restrict__ emb,
                 const float* __restrict__ b_tree,
                 const float* __restrict__ W_cls,
                 const float* __restrict__ b_cls,
                 float* __restrict__ out)
{
    extern __shared__ float smem[];
    float* WT_s = smem;                   // 32768 floats (128 KB)
    float* reps = smem + 32768;           // 16384 floats (64 KB)
    float* b_s  = smem + 32768 + 16384;   // 128 floats

    const int tid  = threadIdx.x;
    const int lane = tid & 31;
    const int warp = tid >> 5;
    const int b    = blockIdx.x;

    // Stage transposed W into smem (coalesced global, conflict-free smem)
    {
        const float4* src = reinterpret_cast<const float4*>(g_WT);
        float4* dst = reinterpret_cast<float4*>(WT_s);
        for (int i = tid; i < 8192; i += NTHREADS) dst[i] = src[i];
    }
    if (tid < 128) b_s[tid] = b_tree[tid];

    // Embedding gather: 128 rows x 128 floats, float4-coalesced
    const int is64 = g_tok_is64;
    const long long* tok64 = reinterpret_cast<const long long*>(tokens_raw) + (long long)b * 128;
    const int*       tok32 = reinterpret_cast<const int*>(tokens_raw) + b * 128;
    float4* reps4 = reinterpret_cast<float4*>(reps);
    const float4* emb4 = reinterpret_cast<const float4*>(emb);
    for (int i = tid; i < 128 * 32; i += NTHREADS) {
        int row = i >> 5;
        int q   = i & 31;
        int t = is64 ? (int)__ldg(&tok64[row]) : __ldg(&tok32[row]);
        reps4[row * 32 + q] = __ldg(&emb4[(long long)t * 32 + q]);
    }
    __syncthreads();

    const float4* WT4 = reinterpret_cast<const float4*>(WT_s);
    const float4* b4p = reinterpret_cast<const float4*>(b_s);

    for (int lvl = 0; lvl < 7; ++lvl) {
        const int N = 64 >> lvl;                      // nodes produced this level
        const int R = (N >= 32) ? 4 : (N == 16 ? 2 : 1);
        const int groups = N / R;
        float4 y0[4], y1[4];
        const bool has0 = warp < groups;
        const bool has1 = (warp + 8) < groups;        // only at lvl 0 (groups=16, R=4)

        if (has0) {
            int n0 = warp * R;
            if (R == 4)      compute_group<4>(reps, WT4, b4p, n0, lane, y0);
            else if (R == 2) compute_group<2>(reps, WT4, b4p, n0, lane, y0);
            else             compute_group<1>(reps, WT4, b4p, n0, lane, y0);
        }
        if (has1) {
            int n1 = (warp + 8) * 4;
            compute_group<4>(reps, WT4, b4p, n1, lane, y1);
        }
        __syncthreads();   // all reads of this level done before in-place writes
        if (has0) {
            int n0 = warp * R;
            for (int r = 0; r < R; ++r)
                reinterpret_cast<float4*>(reps + (n0 + r) * 128)[lane] = y0[r];
        }
        if (has1) {
            int n1 = (warp + 8) * 4;
#pragma unroll
            for (int r = 0; r < 4; ++r)
                reinterpret_cast<float4*>(reps + (n1 + r) * 128)[lane] = y1[r];
        }
        __syncthreads();
    }

    // Classifier: out[o] = b_cls[o] + sum_h reps[0][h] * W_cls[o][h], o in {0,1,2}
    if (warp == 0) {
        float s0 = 0.f, s1 = 0.f, s2 = 0.f;
#pragma unroll
        for (int k = 0; k < 4; ++k) {
            int h = lane + 32 * k;
            float rv = reps[h];
            s0 += rv * __ldg(&W_cls[h]);
            s1 += rv * __ldg(&W_cls[128 + h]);
            s2 += rv * __ldg(&W_cls[256 + h]);
        }
#pragma unroll
        for (int off = 16; off; off >>= 1) {
            s0 += __shfl_xor_sync(0xffffffffu, s0, off);
            s1 += __shfl_xor_sync(0xffffffffu, s1, off);
            s2 += __shfl_xor_sync(0xffffffffu, s2, off);
        }
        if (lane == 0) {
            out[b * 3 + 0] = s0 + __ldg(&b_cls[0]);
            out[b * 3 + 1] = s1 + __ldg(&b_cls[1]);
            out[b * 3 + 2] = s2 + __ldg(&b_cls[2]);
        }
    }
}

extern "C" void kernel_launch(void* const* d_in, const int* in_sizes, int n_in,
                              void* d_out, int out_size)
{
    const void*  tokens = d_in[0];
    const float* emb    = (const float*)d_in[1];
    const float* W_tree = (const float*)d_in[2];
    const float* b_tree = (const float*)d_in[3];
    const float* W_cls  = (const float*)d_in[4];
    const float* b_cls  = (const float*)d_in[5];
    float* out = (float*)d_out;

    cudaFuncSetAttribute(tree_kernel, cudaFuncAttributeMaxDynamicSharedMemorySize, 197120);

    prep_kernel<<<128, 256>>>(W_tree, (const int*)tokens);
    tree_kernel<<<4096, NTHREADS, 197120>>>(tokens, emb, b_tree, W_cls, b_cls, out);
}

// round 2
// speedup vs baseline: 2.3706x; 2.3706x over previous
#include <cuda_runtime.h>
#include <cstdint>

#define THREADS 256
#define LDA 132   // 128 + 4 pad: 132 mod 32 = 4 -> conflict-free fragment loads

// Ping-pong scratch (static device arrays; no runtime allocation)
__device__ float g_bufA[4096u * 64u * 128u];   // 134 MB
__device__ float g_bufB[4096u * 32u * 128u];   //  67 MB
__device__ int   g_tok_is64;

// Detect int64 vs int32 token buffer (JAX may silently emit int32).
__global__ void prep_kernel(const int* __restrict__ tok32) {
    if (threadIdx.x == 0) {
        int is64 = 1;
        for (int k = 1; k < 256; k += 2)
            if (tok32[k] != 0) { is64 = 0; break; }
        g_tok_is64 = is64;
    }
}

__device__ __forceinline__ uint32_t f2tf(float x) {
    uint32_t r;
    asm("cvt.rna.tf32.f32 %0, %1;" : "=r"(r) : "f"(x));
    return r;
}

// One tree level as GEMM: out[M,128] = tanh(A[M,256] @ W^T + b)
// A is the previous level's reps buffer viewed [M,256] (pair-concat is contiguous).
// GATHER=true: level 0, A rows gathered from embedding via tokens.
template <bool GATHER>
__global__ __launch_bounds__(THREADS, 1)
void gemm_kernel(const float* __restrict__ A,
                 const void*  __restrict__ tokens,
                 const float* __restrict__ emb,
                 const float* __restrict__ W,      // [128,256] row-major: W[e][h]
                 const float* __restrict__ bias,   // [128]
                 float* __restrict__ out)          // [M,128]
{
    extern __shared__ uint32_t smem[];
    uint32_t* As   = smem;               // 128 x LDA (tf32 bits)
    uint32_t* Bs   = smem + 128 * LDA;   // 128 x LDA
    float*    b_s  = (float*)(smem + 2 * 128 * LDA);  // 128
    int*      tok_s = (int*)(b_s + 128);              // 128

    const int tid  = threadIdx.x;
    const int lane = tid & 31;
    const int warp = tid >> 5;
    const int m0   = blockIdx.x * 128;

    if (tid < 128) b_s[tid] = bias[tid];

    float acc[2][8][4];
#pragma unroll
    for (int mi = 0; mi < 2; ++mi)
#pragma unroll
        for (int ni = 0; ni < 8; ++ni)
#pragma unroll
            for (int j = 0; j < 4; ++j) acc[mi][ni][j] = 0.f;

    const int wm = (warp >> 1) * 32;   // warp tile 32x64 in a 128x128 CTA tile
    const int wn = (warp & 1) * 64;
    const int q  = lane >> 2;          // 0..7
    const int tg = lane & 3;           // 0..3

    const int is64 = GATHER ? g_tok_is64 : 0;

    for (int kc = 0; kc < 2; ++kc) {   // K=256 in two chunks of 128
        if (GATHER) {
            __syncthreads();
            if (tid < 128) {
                int m = m0 + tid;
                int b = m >> 6, n = m & 63;
                long long ti = (long long)b * 128 + 2 * n + kc;  // left / right leaf
                tok_s[tid] = is64 ? (int)((const long long*)tokens)[ti]
                                  : ((const int*)tokens)[ti];
            }
            __syncthreads();
        }
        // A tile: 128 rows x 128 cols, float4-coalesced, cvt->tf32 into smem
        for (int i = tid; i < 128 * 32; i += THREADS) {
            int r = i >> 5, c4 = i & 31;
            float4 v;
            if (GATHER) {
                long long t = tok_s[r];
                v = __ldg((const float4*)emb + t * 32 + c4);
            } else {
                v = __ldg((const float4*)A + (long long)(m0 + r) * 64 + kc * 32 + c4);
            }
            uint32_t* dst = As + r * LDA + c4 * 4;
            dst[0] = f2tf(v.x); dst[1] = f2tf(v.y);
            dst[2] = f2tf(v.z); dst[3] = f2tf(v.w);
        }
        // B tile: W[e][kc*128 + k], stored Bs[n=e][k]
        for (int i = tid; i < 128 * 32; i += THREADS) {
            int r = i >> 5, c4 = i & 31;
            float4 v = __ldg((const float4*)W + r * 64 + kc * 32 + c4);
            uint32_t* dst = Bs + r * LDA + c4 * 4;
            dst[0] = f2tf(v.x); dst[1] = f2tf(v.y);
            dst[2] = f2tf(v.z); dst[3] = f2tf(v.w);
        }
        __syncthreads();

#pragma unroll
        for (int ks = 0; ks < 16; ++ks) {
            const int k0 = ks * 8;
            uint32_t a[2][4];
#pragma unroll
            for (int mi = 0; mi < 2; ++mi) {
                const uint32_t* ap = As + (wm + mi * 16 + q) * LDA + k0 + tg;
                a[mi][0] = ap[0];
                a[mi][1] = ap[8 * LDA];
                a[mi][2] = ap[4];
                a[mi][3] = ap[8 * LDA + 4];
            }
#pragma unroll
            for (int ni = 0; ni < 8; ++ni) {
                const uint32_t* bp = Bs + (wn + ni * 8 + q) * LDA + k0 + tg;
                uint32_t b0 = bp[0], b1 = bp[4];
#pragma unroll
                for (int mi = 0; mi < 2; ++mi) {
                    asm volatile(
                        "mma.sync.aligned.m16n8k8.row.col.f32.tf32.tf32.f32 "
                        "{%0,%1,%2,%3}, {%4,%5,%6,%7}, {%8,%9}, {%0,%1,%2,%3};"
                        : "+f"(acc[mi][ni][0]), "+f"(acc[mi][ni][1]),
                          "+f"(acc[mi][ni][2]), "+f"(acc[mi][ni][3])
                        : "r"(a[mi][0]), "r"(a[mi][1]), "r"(a[mi][2]), "r"(a[mi][3]),
                          "r"(b0), "r"(b1));
                }
            }
        }
        __syncthreads();
    }

    // Epilogue: bias + tanh, float2 stores (lanes 0..3 cover 32B contiguous)
#pragma unroll
    for (int mi = 0; mi < 2; ++mi) {
#pragma unroll
        for (int ni = 0; ni < 8; ++ni) {
            int col = wn + ni * 8 + 2 * tg;
            float bv0 = b_s[col], bv1 = b_s[col + 1];
            int r0 = m0 + wm + mi * 16 + q;
            float2 v0, v1;
            v0.x = tanhf(acc[mi][ni][0] + bv0);
            v0.y = tanhf(acc[mi][ni][1] + bv1);
            v1.x = tanhf(acc[mi][ni][2] + bv0);
            v1.y = tanhf(acc[mi][ni][3] + bv1);
            *(float2*)(out + (long long)r0 * 128 + col)       = v0;
            *(float2*)(out + (long long)(r0 + 8) * 128 + col) = v1;
        }
    }
}

// out[b,o] = roots[b] . W_cls[o] + b_cls[o]; one warp per batch row
__global__ void cls_kernel(const float* __restrict__ reps,
                           const float* __restrict__ Wc,
                           const float* __restrict__ bc,
                           float* __restrict__ out)
{
    int warp = threadIdx.x >> 5, lane = threadIdx.x & 31;
    int row = blockIdx.x * 8 + warp;
    float4 rv = ((const float4*)(reps + (long long)row * 128))[lane];
    float s[3];
#pragma unroll
    for (int o = 0; o < 3; ++o) {
        float4 wv = __ldg((const float4*)(Wc + o * 128) + lane);
        s[o] = rv.x * wv.x + rv.y * wv.y + rv.z * wv.z + rv.w * wv.w;
    }
#pragma unroll
    for (int off = 16; off; off >>= 1)
#pragma unroll
        for (int o = 0; o < 3; ++o) s[o] += __shfl_xor_sync(~0u, s[o], off);
    if (lane < 3) out[row * 3 + lane] = s[lane] + __ldg(&bc[lane]);
}

extern "C" void kernel_launch(void* const* d_in, const int* in_sizes, int n_in,
                              void* d_out, int out_size)
{
    const void*  tokens = d_in[0];
    const float* emb    = (const float*)d_in[1];
    const float* W_tree = (const float*)d_in[2];
    const float* b_tree = (const float*)d_in[3];
    const float* W_cls  = (const float*)d_in[4];
    const float* b_cls  = (const float*)d_in[5];
    float* out = (float*)d_out;

    float *bufA, *bufB;
    cudaGetSymbolAddress((void**)&bufA, g_bufA);
    cudaGetSymbolAddress((void**)&bufB, g_bufB);

    const size_t smem = (size_t)2 * 128 * LDA * 4 + 1024;  // ~136 KB
    cudaFuncSetAttribute(gemm_kernel<true>,  cudaFuncAttributeMaxDynamicSharedMemorySize, smem);
    cudaFuncSetAttribute(gemm_kernel<false>, cudaFuncAttributeMaxDynamicSharedMemorySize, smem);

    prep_kernel<<<1, 32>>>((const int*)tokens);

    // Level 0: M = 4096*64 = 262144 rows, gather fused
    gemm_kernel<true><<<2048, THREADS, smem>>>(nullptr, tokens, emb, W_tree, b_tree, bufA);

    // Levels 1..6
    float* src = bufA;
    float* dst = bufB;
    int M = 131072;
    for (int l = 1; l < 7; ++l) {
        gemm_kernel<false><<<M / 128, THREADS, smem>>>(src, nullptr, nullptr,
                                                       W_tree, b_tree, dst);
        float* t = src; src = dst; dst = t;
        M >>= 1;
    }
    // src now holds level-6 output: [4096, 128]
    cls_kernel<<<512, 256>>>(src, W_cls, b_cls, out);
}

// round 5
// speedup vs baseline: 3.5063x; 1.4791x over previous
#include <cuda_runtime.h>
#include <cstdint>

#define THREADS 512
#define LDS_ROW 68                       // 64 + 4 pad (floats) -> conflict-free frags
#define STAGE_FLOATS (2 * 128 * LDS_ROW) // A(128x68) + B(128x68)
#define SMEM_BYTES (3 * STAGE_FLOATS * 4 + 512 + 1024 + 256)

__device__ float g_bufA[262144ull * 128ull];   // level outputs (ping)
__device__ float g_bufB[131072ull * 128ull];   // level outputs (pong)
__device__ float g_Wtf[128 * 256];             // W_tree as tf32 bits
__device__ float g_embtf[100000ull * 128ull];  // embedding as tf32 bits
__device__ int   g_tok_is64;

__global__ void prep_tok(const int* __restrict__ tok32) {
    if (threadIdx.x == 0) {
        int is64 = 1;
        for (int k = 1; k < 256; k += 2)
            if (tok32[k] != 0) { is64 = 0; break; }
        g_tok_is64 = is64;
    }
}

__device__ __forceinline__ uint32_t f2tf(float x) {
    uint32_t r;
    asm("cvt.rna.tf32.f32 %0, %1;" : "=r"(r) : "f"(x));
    return r;
}

__global__ void prep_w(const float* __restrict__ W) {
    int i = blockIdx.x * 256 + threadIdx.x;
    if (i < 128 * 256) g_Wtf[i] = __uint_as_float(f2tf(W[i]));
}

__global__ void prep_emb(const float* __restrict__ emb) {
    const float4* src = (const float4*)emb;
    float4* dst = (float4*)g_embtf;
    const int n4 = 100000 * 32;
    for (int i = blockIdx.x * blockDim.x + threadIdx.x; i < n4;
         i += gridDim.x * blockDim.x) {
        float4 v = src[i];
        float4 o;
        o.x = __uint_as_float(f2tf(v.x));
        o.y = __uint_as_float(f2tf(v.y));
        o.z = __uint_as_float(f2tf(v.z));
        o.w = __uint_as_float(f2tf(v.w));
        dst[i] = o;
    }
}

__device__ __forceinline__ float tanh_fast(float x) {
    float xc = fminf(fmaxf(x, -20.f), 20.f);
    float t = __expf(2.f * xc);
    return __fdividef(t - 1.f, t + 1.f);
}

__device__ __forceinline__ void cp16(uint32_t dst, const void* src) {
    asm volatile("cp.async.cg.shared.global [%0], [%1], 16;" :: "r"(dst), "l"(src));
}

// out[M,128] = tanh(A[M,256] @ W^T + b); A rows are contiguous pair-concats.
// GATHER: level 0, rows gathered from tf32 embedding. TFOUT: store tf32 bits.
template <bool GATHER, bool TFOUT>
__global__ __launch_bounds__(THREADS, 1)
void gemm_kernel(const float* __restrict__ Asrc,
                 const void*  __restrict__ tokens,
                 const float* __restrict__ bias,
                 float* __restrict__ out)
{
    extern __shared__ uint32_t sm[];
    float* bias_s = (float*)(sm + 3 * STAGE_FLOATS);
    int*   tok_s  = (int*)(bias_s + 128);
    const uint32_t smem_base = (uint32_t)__cvta_generic_to_shared(sm);

    const int tid  = threadIdx.x;
    const int lane = tid & 31;
    const int warp = tid >> 5;
    const int m0   = blockIdx.x * 128;

    if (tid < 128) bias_s[tid] = bias[tid];
    if (GATHER) {
        if (tid < 256) {
            int r = tid >> 1, side = tid & 1;
            int gm = m0 + r;
            long long ti = (long long)(gm >> 6) * 128 + 2 * (gm & 63) + side;
            tok_s[r * 2 + side] = g_tok_is64 ? (int)((const long long*)tokens)[ti]
                                             : ((const int*)tokens)[ti];
        }
        __syncthreads();
    }

    // Issue one K-chunk (64 cols) of A and B into stage s.
    auto issue_load = [&](int kc, int s) {
        const uint32_t As = smem_base + (uint32_t)(s * STAGE_FLOATS) * 4u;
        const uint32_t Bs = As + 128u * LDS_ROW * 4u;
#pragma unroll
        for (int p = 0; p < 4; ++p) {
            int idx = tid + p * THREADS;        // 0..2047
            int row = idx >> 4, c16 = idx & 15; // 16B units within a 64-float row
            const float* sa;
            if (GATHER) {
                long long t = tok_s[2 * row + (kc >> 1)];
                sa = g_embtf + t * 128 + (kc & 1) * 64 + c16 * 4;
            } else {
                sa = Asrc + (long long)(m0 + row) * 256 + kc * 64 + c16 * 4;
            }
            cp16(As + (uint32_t)(row * LDS_ROW + c16 * 4) * 4u, sa);
            const float* sb = g_Wtf + row * 256 + kc * 64 + c16 * 4;
            cp16(Bs + (uint32_t)(row * LDS_ROW + c16 * 4) * 4u, sb);
        }
        asm volatile("cp.async.commit_group;");
    };

    float acc[2][4][4];
#pragma unroll
    for (int mi = 0; mi < 2; ++mi)
#pragma unroll
        for (int ni = 0; ni < 4; ++ni)
#pragma unroll
            for (int j = 0; j < 4; ++j) acc[mi][ni][j] = 0.f;

    const int wm = (warp & 3) * 32;   // 4 m-blocks of 32
    const int wn = (warp >> 2) * 32;  // 4 n-blocks of 32
    const int q  = lane >> 2;
    const int tg = lane & 3;

    issue_load(0, 0);
    issue_load(1, 1);

#pragma unroll
    for (int kc = 0; kc < 4; ++kc) {
        if (kc == 3) asm volatile("cp.async.wait_group 0;");
        else         asm volatile("cp.async.wait_group 1;");
        __syncthreads();
        if (kc < 2) issue_load(kc + 2, (kc + 2) % 3);

        const uint32_t* As = sm + (kc % 3) * STAGE_FLOATS;
        const uint32_t* Bs = As + 128 * LDS_ROW;
#pragma unroll
        for (int ks = 0; ks < 8; ++ks) {
            const int k0 = ks * 8;
            uint32_t a[2][4];
#pragma unroll
            for (int mi = 0; mi < 2; ++mi) {
                const uint32_t* ap = As + (wm + mi * 16 + q) * LDS_ROW + k0 + tg;
                a[mi][0] = ap[0];
                a[mi][1] = ap[8 * LDS_ROW];
                a[mi][2] = ap[4];
                a[mi][3] = ap[8 * LDS_ROW + 4];
            }
#pragma unroll
            for (int ni = 0; ni < 4; ++ni) {
                const uint32_t* bp = Bs + (wn + ni * 8 + q) * LDS_ROW + k0 + tg;
                uint32_t b0 = bp[0], b1 = bp[4];
#pragma unroll
                for (int mi = 0; mi < 2; ++mi) {
                    asm volatile(
                        "mma.sync.aligned.m16n8k8.row.col.f32.tf32.tf32.f32 "
                        "{%0,%1,%2,%3}, {%4,%5,%6,%7}, {%8,%9}, {%0,%1,%2,%3};"
                        : "+f"(acc[mi][ni][0]), "+f"(acc[mi][ni][1]),
                          "+f"(acc[mi][ni][2]), "+f"(acc[mi][ni][3])
                        : "r"(a[mi][0]), "r"(a[mi][1]), "r"(a[mi][2]), "r"(a[mi][3]),
                          "r"(b0), "r"(b1));
                }
            }
        }
        __syncthreads();
    }

    // Epilogue: bias + fast tanh; levels 0-5 store tf32 bits, level 6 fp32.
#pragma unroll
    for (int mi = 0; mi < 2; ++mi) {
#pragma unroll
        for (int ni = 0; ni < 4; ++ni) {
            int col = wn + ni * 8 + 2 * tg;
            float bv0 = bias_s[col], bv1 = bias_s[col + 1];
            int r0 = m0 + wm + mi * 16 + q;
            float t0 = tanh_fast(acc[mi][ni][0] + bv0);
            float t1 = tanh_fast(acc[mi][ni][1] + bv1);
            float t2 = tanh_fast(acc[mi][ni][2] + bv0);
            float t3 = tanh_fast(acc[mi][ni][3] + bv1);
            float2 v0, v1;
            if (TFOUT) {
                v0.x = __uint_as_float(f2tf(t0)); v0.y = __uint_as_float(f2tf(t1));
                v1.x = __uint_as_float(f2tf(t2)); v1.y = __uint_as_float(f2tf(t3));
            } else {
                v0.x = t0; v0.y = t1; v1.x = t2; v1.y = t3;
            }
            *(float2*)(out + (long long)r0 * 128 + col)       = v0;
            *(float2*)(out + (long long)(r0 + 8) * 128 + col) = v1;
        }
    }
}

__global__ void cls_kernel(const float* __restrict__ reps,
                           const float* __restrict__ Wc,
                           const float* __restrict__ bc,
                           float* __restrict__ out)
{
    int warp = threadIdx.x >> 5, lane = threadIdx.x & 31;
    int row = blockIdx.x * 8 + warp;
    float4 rv = ((const float4*)(reps + (long long)row * 128))[lane];
    float s[3];
#pragma unroll
    for (int o = 0; o < 3; ++o) {
        float4 wv = __ldg((const float4*)(Wc + o * 128) + lane);
        s[o] = rv.x * wv.x + rv.y * wv.y + rv.z * wv.z + rv.w * wv.w;
    }
#pragma unroll
    for (int off = 16; off; off >>= 1)
#pragma unroll
        for (int o = 0; o < 3; ++o) s[o] += __shfl_xor_sync(~0u, s[o], off);
    if (lane < 3) out[row * 3 + lane] = s[lane] + __ldg(&bc[lane]);
}

extern "C" void kernel_launch(void* const* d_in, const int* in_sizes, int n_in,
                              void* d_out, int out_size)
{
    const void*  tokens = d_in[0];
    const float* emb    = (const float*)d_in[1];
    const float* W_tree = (const float*)d_in[2];
    const float* b_tree = (const float*)d_in[3];
    const float* W_cls  = (const float*)d_in[4];
    const float* b_cls  = (const float*)d_in[5];
    float* out = (float*)d_out;

    float *bufA, *bufB;
    cudaGetSymbolAddress((void**)&bufA, g_bufA);
    cudaGetSymbolAddress((void**)&bufB, g_bufB);

    cudaFuncSetAttribute(gemm_kernel<true, true>,
                         cudaFuncAttributeMaxDynamicSharedMemorySize, SMEM_BYTES);
    cudaFuncSetAttribute(gemm_kernel<false, true>,
                         cudaFuncAttributeMaxDynamicSharedMemorySize, SMEM_BYTES);
    cudaFuncSetAttribute(gemm_kernel<false, false>,
                         cudaFuncAttributeMaxDynamicSharedMemorySize, SMEM_BYTES);

    prep_tok<<<1, 32>>>((const int*)tokens);
    prep_w<<<128, 256>>>(W_tree);
    prep_emb<<<4096, 512>>>(emb);

    // Level 0: M = 262144 rows (gather fused), -> bufA
    gemm_kernel<true, true><<<2048, THREADS, SMEM_BYTES>>>(nullptr, tokens, b_tree, bufA);

    // Levels 1..5 (tf32-bit outputs), level 6 (fp32 output)
    float* src = bufA;
    float* dst = bufB;
    int M = 131072;
    for (int l = 1; l < 7; ++l) {
        if (l < 6)
            gemm_kernel<false, true><<<M / 128, THREADS, SMEM_BYTES>>>(src, nullptr, b_tree, dst);
        else
            gemm_kernel<false, false><<<M / 128, THREADS, SMEM_BYTES>>>(src, nullptr, b_tree, dst);
        float* t = src; src = dst; dst = t;
        M >>= 1;
    }
    // src holds level-6 output [4096,128]
    cls_kernel<<<512, 256>>>(src, W_cls, b_cls, out);
}

// round 8
// speedup vs baseline: 3.9768x; 1.1342x over previous
#include <cuda_runtime.h>
#include <cstdint>

// ---------------- buffers ----------------
__device__ float g_bufA[131072ull * 128ull];   // l1 (67MB) then l5
__device__ float g_bufB[32768ull * 128ull];    // l3 then l6
__device__ float g_Wtf[128 * 256];             // W_tree tf32 bits
__device__ float g_embtf[100000ull * 128ull];  // embedding tf32 bits
__device__ int   g_tok_is64;

// ---------------- prep ----------------
__global__ void prep_tok(const int* __restrict__ tok32) {
    __shared__ int bad;
    if (threadIdx.x == 0) bad = 0;
    __syncthreads();
    if (threadIdx.x < 128 && tok32[2 * threadIdx.x + 1] != 0) atomicAdd(&bad, 1);
    __syncthreads();
    if (threadIdx.x == 0) g_tok_is64 = (bad == 0);
}

__device__ __forceinline__ uint32_t f2tf(float x) {
    uint32_t r;
    asm("cvt.rna.tf32.f32 %0, %1;" : "=r"(r) : "f"(x));
    return r;
}

__global__ void prep_w(const float* __restrict__ W) {
    int i = blockIdx.x * 256 + threadIdx.x;
    if (i < 128 * 256) g_Wtf[i] = __uint_as_float(f2tf(W[i]));
}

__global__ void prep_emb(const float* __restrict__ emb) {
    const float4* src = (const float4*)emb;
    float4* dst = (float4*)g_embtf;
    const int n4 = 100000 * 32;
    for (int i = blockIdx.x * blockDim.x + threadIdx.x; i < n4;
         i += gridDim.x * blockDim.x) {
        float4 v = src[i];
        float4 o;
        o.x = __uint_as_float(f2tf(v.x));
        o.y = __uint_as_float(f2tf(v.y));
        o.z = __uint_as_float(f2tf(v.z));
        o.w = __uint_as_float(f2tf(v.w));
        dst[i] = o;
    }
}

// ---------------- helpers ----------------
__device__ __forceinline__ float tanh_fast(float x) {
    float xc = fminf(fmaxf(x, -20.f), 20.f);
    float t = __expf(2.f * xc);
    return __fdividef(t - 1.f, t + 1.f);
}

__device__ __forceinline__ void cp16(uint32_t dst, const void* src) {
    asm volatile("cp.async.cg.shared.global [%0], [%1], 16;" :: "r"(dst), "l"(src));
}

__device__ __forceinline__ void ldsm4(uint32_t addr, uint32_t* r) {
    asm volatile("ldmatrix.sync.aligned.m8n8.x4.shared.b16 {%0,%1,%2,%3}, [%4];"
                 : "=r"(r[0]), "=r"(r[1]), "=r"(r[2]), "=r"(r[3]) : "r"(addr));
}

__device__ __forceinline__ void mma_tf32(float* d, const uint32_t* a,
                                         uint32_t b0, uint32_t b1) {
    asm volatile(
        "mma.sync.aligned.m16n8k8.row.col.f32.tf32.tf32.f32 "
        "{%0,%1,%2,%3},{%4,%5,%6,%7},{%8,%9},{%0,%1,%2,%3};"
        : "+f"(d[0]), "+f"(d[1]), "+f"(d[2]), "+f"(d[3])
        : "r"(a[0]), "r"(a[1]), "r"(a[2]), "r"(a[3]), "r"(b0), "r"(b1));
}

__device__ __forceinline__ void sts64(uint32_t addr, uint32_t v0, uint32_t v1) {
    asm volatile("st.shared.v2.b32 [%0], {%1,%2};" :: "r"(addr), "r"(v0), "r"(v1));
}

// ---------------- fused two-level kernel ----------------
// Phase 1: 256 rows of level-l output = tanh(A1[256,256] @ W^T + b) -> smem INT
// Phase 2: 128 rows of level-(l+1)     = tanh(INT[128,256] @ W^T + b) -> global
#define F_ABASE 0u
#define F_BBASE 65536u
#define F_INT   98304u
#define F_BIAS  229376u
#define F_TOK   229888u
#define F_SMEM  231936u

template <bool GATHER>
__global__ __launch_bounds__(512, 1)
void fused_tc(const float* __restrict__ Asrc, const void* __restrict__ tokens,
              const float* __restrict__ bias, float* __restrict__ out)
{
    extern __shared__ char smem[];
    const uint32_t sb = (uint32_t)__cvta_generic_to_shared(smem);
    float* bias_s = (float*)(smem + F_BIAS);
    int*   tok_s  = (int*)(smem + F_TOK);

    const int tid = threadIdx.x, lane = tid & 31, warp = tid >> 5;
    const int m0p = blockIdx.x * 256;
    const int jj = lane >> 3, rr = lane & 7;
    const int arow = (jj & 1) * 8 + rr, kqa = jj >> 1;     // A ldsm lane map
    const int brow = (jj >> 1) * 8 + rr, kqb = jj & 1;     // B ldsm lane map
    const int q = lane >> 2, tg = lane & 3;

    if (tid < 128) bias_s[tid] = bias[tid];
    if (GATHER) {
        const int is64 = g_tok_is64;
        int j = tid >> 1, side = tid & 1;
        int pr = m0p + j;
        long long ti = (long long)(pr >> 6) * 128 + 2 * (pr & 63) + side;
        tok_s[tid] = is64 ? (int)((const long long*)tokens)[ti]
                          : ((const int*)tokens)[ti];
    }
    __syncthreads();

    auto issueA1 = [&](int kc) {
        const uint32_t d = sb + F_ABASE + (uint32_t)(kc & 1) * 32768u;
#pragma unroll
        for (int p = 0; p < 4; ++p) {
            int idx = tid + p * 512;
            int row = idx >> 3, u = idx & 7;
            const float* src;
            if (GATHER) {
                long long tk = tok_s[2 * row + (kc >> 2)];
                src = g_embtf + tk * 128 + (kc & 3) * 32 + u * 4;
            } else {
                src = Asrc + (long long)(m0p + row) * 256 + kc * 32 + u * 4;
            }
            cp16(d + (uint32_t)(row * 128 + ((u ^ (row & 7)) << 4)), src);
        }
    };
    auto issueB = [&](int kc) {
        const uint32_t d = sb + F_BBASE + (uint32_t)(kc & 1) * 16384u;
#pragma unroll
        for (int p = 0; p < 2; ++p) {
            int idx = tid + p * 512;
            int row = idx >> 3, u = idx & 7;
            cp16(d + (uint32_t)(row * 128 + ((u ^ (row & 7)) << 4)),
                 g_Wtf + row * 256 + kc * 32 + u * 4);
        }
    };

    // ================= phase 1: warp tile 64x32 =================
    float acc[4][4][4];
#pragma unroll
    for (int a = 0; a < 4; ++a)
#pragma unroll
        for (int b = 0; b < 4; ++b)
#pragma unroll
            for (int c = 0; c < 4; ++c) acc[a][b][c] = 0.f;

    const int wm1 = (warp & 3) * 64, wn1 = (warp >> 2) * 32;

    issueA1(0); issueB(0); asm volatile("cp.async.commit_group;");
    issueA1(1); issueB(1); asm volatile("cp.async.commit_group;");

    for (int kc = 0; kc < 8; ++kc) {
        if (kc < 7) asm volatile("cp.async.wait_group 1;");
        else        asm volatile("cp.async.wait_group 0;");
        __syncthreads();
        const uint32_t Ab = sb + F_ABASE + (uint32_t)(kc & 1) * 32768u;
        const uint32_t Bb = sb + F_BBASE + (uint32_t)(kc & 1) * 16384u;
#pragma unroll
        for (int ks = 0; ks < 4; ++ks) {
            uint32_t af[4][4], bf[2][4];
#pragma unroll
            for (int mi = 0; mi < 4; ++mi)
                ldsm4(Ab + (uint32_t)((wm1 + mi * 16 + arow) * 128 +
                      ((((ks << 1) | kqa) ^ rr) << 4)), af[mi]);
#pragma unroll
            for (int nt = 0; nt < 2; ++nt)
                ldsm4(Bb + (uint32_t)((wn1 + nt * 16 + brow) * 128 +
                      ((((ks << 1) | kqb) ^ rr) << 4)), bf[nt]);
#pragma unroll
            for (int ni = 0; ni < 4; ++ni) {
                uint32_t b0 = bf[ni >> 1][(ni & 1) * 2];
                uint32_t b1 = bf[ni >> 1][(ni & 1) * 2 + 1];
#pragma unroll
                for (int mi = 0; mi < 4; ++mi) mma_tf32(acc[mi][ni], af[mi], b0, b1);
            }
        }
        __syncthreads();
        if (kc < 6) { issueA1(kc + 2); issueB(kc + 2); asm volatile("cp.async.commit_group;"); }
    }

    // phase-1 epilogue -> INT in phase-2 chunk-swizzled layout
    auto emit1 = [&](int r, int c, float v0, float v1) {
        uint32_t t0 = f2tf(tanh_fast(v0 + bias_s[c]));
        uint32_t t1 = f2tf(tanh_fast(v1 + bias_s[c + 1]));
        int R = r >> 1, c2 = ((r & 1) << 7) + c;
        int ch = c2 >> 5, k = c2 & 31;
        uint32_t off = sb + F_INT + (uint32_t)(ch * 16384 + R * 128 +
                       (((k >> 2) ^ (R & 7)) << 4) + ((k & 3) << 2));
        sts64(off, t0, t1);
    };
#pragma unroll
    for (int mi = 0; mi < 4; ++mi)
#pragma unroll
        for (int ni = 0; ni < 4; ++ni) {
            int col = wn1 + ni * 8 + 2 * tg;
            int r0 = wm1 + mi * 16 + q;
            emit1(r0,     col, acc[mi][ni][0], acc[mi][ni][1]);
            emit1(r0 + 8, col, acc[mi][ni][2], acc[mi][ni][3]);
        }
    __syncthreads();

    // ================= phase 2: warp tile 32x32, A = INT =================
    float ac2[2][4][4];
#pragma unroll
    for (int a = 0; a < 2; ++a)
#pragma unroll
        for (int b = 0; b < 4; ++b)
#pragma unroll
            for (int c = 0; c < 4; ++c) ac2[a][b][c] = 0.f;

    const int wm2 = (warp & 3) * 32, wn2 = (warp >> 2) * 32;

    issueB(0); asm volatile("cp.async.commit_group;");
    issueB(1); asm volatile("cp.async.commit_group;");

    for (int kc = 0; kc < 8; ++kc) {
        if (kc < 7) asm volatile("cp.async.wait_group 1;");
        else        asm volatile("cp.async.wait_group 0;");
        __syncthreads();
        const uint32_t Ab = sb + F_INT + (uint32_t)kc * 16384u;
        const uint32_t Bb = sb + F_BBASE + (uint32_t)(kc & 1) * 16384u;
#pragma unroll
        for (int ks = 0; ks < 4; ++ks) {
            uint32_t af[2][4], bf[2][4];
#pragma unroll
            for (int mi = 0; mi < 2; ++mi)
                ldsm4(Ab + (uint32_t)((wm2 + mi * 16 + arow) * 128 +
                      ((((ks << 1) | kqa) ^ rr) << 4)), af[mi]);
#pragma unroll
            for (int nt = 0; nt < 2; ++nt)
                ldsm4(Bb + (uint32_t)((wn2 + nt * 16 + brow) * 128 +
                      ((((ks << 1) | kqb) ^ rr) << 4)), bf[nt]);
#pragma unroll
            for (int ni = 0; ni < 4; ++ni) {
                uint32_t b0 = bf[ni >> 1][(ni & 1) * 2];
                uint32_t b1 = bf[ni >> 1][(ni & 1) * 2 + 1];
#pragma unroll
                for (int mi = 0; mi < 2; ++mi) mma_tf32(ac2[mi][ni], af[mi], b0, b1);
            }
        }
        __syncthreads();
        if (kc < 6) { issueB(kc + 2); asm volatile("cp.async.commit_group;"); }
    }

    // phase-2 epilogue -> global (tf32 bits; consumed by next GEMM)
    const int cb = blockIdx.x * 128;
#pragma unroll
    for (int mi = 0; mi < 2; ++mi)
#pragma unroll
        for (int ni = 0; ni < 4; ++ni) {
            int col = wn2 + ni * 8 + 2 * tg;
            float bv0 = bias_s[col], bv1 = bias_s[col + 1];
            int r0 = cb + wm2 + mi * 16 + q;
            float2 v0, v1;
            v0.x = __uint_as_float(f2tf(tanh_fast(ac2[mi][ni][0] + bv0)));
            v0.y = __uint_as_float(f2tf(tanh_fast(ac2[mi][ni][1] + bv1)));
            v1.x = __uint_as_float(f2tf(tanh_fast(ac2[mi][ni][2] + bv0)));
            v1.y = __uint_as_float(f2tf(tanh_fast(ac2[mi][ni][3] + bv1)));
            *(float2*)(out + (long long)r0 * 128 + col)       = v0;
            *(float2*)(out + (long long)(r0 + 8) * 128 + col) = v1;
        }
}

// ---------------- single-level kernel (level 6, fp32 out) ----------------
#define S_ABASE 0u
#define S_BBASE 32768u
#define S_BIAS  65536u
#define S_SMEM  66048u

__global__ __launch_bounds__(512, 1)
void single_tc(const float* __restrict__ Asrc, const float* __restrict__ bias,
               float* __restrict__ out)
{
    extern __shared__ char smem[];
    const uint32_t sb = (uint32_t)__cvta_generic_to_shared(smem);
    float* bias_s = (float*)(smem + S_BIAS);

    const int tid = threadIdx.x, lane = tid & 31, warp = tid >> 5;
    const int m0 = blockIdx.x * 128;
    const int jj = lane >> 3, rr = lane & 7;
    const int arow = (jj & 1) * 8 + rr, kqa = jj >> 1;
    const int brow = (jj >> 1) * 8 + rr, kqb = jj & 1;
    const int q = lane >> 2, tg = lane & 3;

    if (tid < 128) bias_s[tid] = bias[tid];
    __syncthreads();

    auto issue = [&](int kc) {
        const uint32_t da = sb + S_ABASE + (uint32_t)(kc & 1) * 16384u;
        const uint32_t db = sb + S_BBASE + (uint32_t)(kc & 1) * 16384u;
#pragma unroll
        for (int p = 0; p < 2; ++p) {
            int idx = tid + p * 512;
            int row = idx >> 3, u = idx & 7;
            cp16(da + (uint32_t)(row * 128 + ((u ^ (row & 7)) << 4)),
                 Asrc + (long long)(m0 + row) * 256 + kc * 32 + u * 4);
            cp16(db + (uint32_t)(row * 128 + ((u ^ (row & 7)) << 4)),
                 g_Wtf + row * 256 + kc * 32 + u * 4);
        }
        asm volatile("cp.async.commit_group;");
    };

    float acc[2][4][4];
#pragma unroll
    for (int a = 0; a < 2; ++a)
#pragma unroll
        for (int b = 0; b < 4; ++b)
#pragma unroll
            for (int c = 0; c < 4; ++c) acc[a][b][c] = 0.f;

    const int wm = (warp & 3) * 32, wn = (warp >> 2) * 32;

    issue(0); issue(1);
    for (int kc = 0; kc < 8; ++kc) {
        if (kc < 7) asm volatile("cp.async.wait_group 1;");
        else        asm volatile("cp.async.wait_group 0;");
        __syncthreads();
        const uint32_t Ab = sb + S_ABASE + (uint32_t)(kc & 1) * 16384u;
        const uint32_t Bb = sb + S_BBASE + (uint32_t)(kc & 1) * 16384u;
#pragma unroll
        for (int ks = 0; ks < 4; ++ks) {
            uint32_t af[2][4], bf[2][4];
#pragma unroll
            for (int mi = 0; mi < 2; ++mi)
                ldsm4(Ab + (uint32_t)((wm + mi * 16 + arow) * 128 +
                      ((((ks << 1) | kqa) ^ rr) << 4)), af[mi]);
#pragma unroll
            for (int nt = 0; nt < 2; ++nt)
                ldsm4(Bb + (uint32_t)((wn + nt * 16 + brow) * 128 +
                      ((((ks << 1) | kqb) ^ rr) << 4)), bf[nt]);
#pragma unroll
            for (int ni = 0; ni < 4; ++ni) {
                uint32_t b0 = bf[ni >> 1][(ni & 1) * 2];
                uint32_t b1 = bf[ni >> 1][(ni & 1) * 2 + 1];
#pragma unroll
                for (int mi = 0; mi < 2; ++mi) mma_tf32(acc[mi][ni], af[mi], b0, b1);
            }
        }
        __syncthreads();
        if (kc < 6) issue(kc + 2);
    }

#pragma unroll
    for (int mi = 0; mi < 2; ++mi)
#pragma unroll
        for (int ni = 0; ni < 4; ++ni) {
            int col = wn + ni * 8 + 2 * tg;
            float bv0 = bias_s[col], bv1 = bias_s[col + 1];
            int r0 = m0 + wm + mi * 16 + q;
            float2 v0, v1;
            v0.x = tanh_fast(acc[mi][ni][0] + bv0);
            v0.y = tanh_fast(acc[mi][ni][1] + bv1);
            v1.x = tanh_fast(acc[mi][ni][2] + bv0);
            v1.y = tanh_fast(acc[mi][ni][3] + bv1);
            *(float2*)(out + (long long)r0 * 128 + col)       = v0;
            *(float2*)(out + (long long)(r0 + 8) * 128 + col) = v1;
        }
}

// ---------------- classifier ----------------
__global__ void cls_kernel(const float* __restrict__ reps,
                           const float* __restrict__ Wc,
                           const float* __restrict__ bc,
                           float* __restrict__ out)
{
    int warp = threadIdx.x >> 5, lane = threadIdx.x & 31;
    int row = blockIdx.x * 8 + warp;
    float4 rv = ((const float4*)(reps + (long long)row * 128))[lane];
    float s[3];
#pragma unroll
    for (int o = 0; o < 3; ++o) {
        float4 wv = __ldg((const float4*)(Wc + o * 128) + lane);
        s[o] = rv.x * wv.x + rv.y * wv.y + rv.z * wv.z + rv.w * wv.w;
    }
#pragma unroll
    for (int off = 16; off; off >>= 1)
#pragma unroll
        for (int o = 0; o < 3; ++o) s[o] += __shfl_xor_sync(~0u, s[o], off);
    if (lane < 3) out[row * 3 + lane] = s[lane] + __ldg(&bc[lane]);
}

// ---------------- launch ----------------
extern "C" void kernel_launch(void* const* d_in, const int* in_sizes, int n_in,
                              void* d_out, int out_size)
{
    const void*  tokens = d_in[0];
    const float* emb    = (const float*)d_in[1];
    const float* W_tree = (const float*)d_in[2];
    const float* b_tree = (const float*)d_in[3];
    const float* W_cls  = (const float*)d_in[4];
    const float* b_cls  = (const float*)d_in[5];
    float* out = (float*)d_out;

    float *bufA, *bufB;
    cudaGetSymbolAddress((void**)&bufA, g_bufA);
    cudaGetSymbolAddress((void**)&bufB, g_bufB);

    cudaFuncSetAttribute(fused_tc<true>,
                         cudaFuncAttributeMaxDynamicSharedMemorySize, F_SMEM);
    cudaFuncSetAttribute(fused_tc<false>,
                         cudaFuncAttributeMaxDynamicSharedMemorySize, F_SMEM);
    cudaFuncSetAttribute(single_tc,
                         cudaFuncAttributeMaxDynamicSharedMemorySize, S_SMEM);

    prep_tok<<<1, 128>>>((const int*)tokens);
    prep_w<<<128, 256>>>(W_tree);
    prep_emb<<<4096, 512>>>(emb);

    // F0: levels 0+1 (gather fused) -> bufA holds l1 [131072,128]
    fused_tc<true><<<1024, 512, F_SMEM>>>(nullptr, tokens, b_tree, bufA);
    // F1: levels 2+3 -> bufB holds l3 [32768,128]
    fused_tc<false><<<256, 512, F_SMEM>>>(bufA, nullptr, b_tree, bufB);
    // F2: levels 4+5 -> bufA holds l5 [8192,128]
    fused_tc<false><<<64, 512, F_SMEM>>>(bufB, nullptr, b_tree, bufA);
    // level 6 -> bufB holds roots [4096,128] fp32
    single_tc<<<32, 512, S_SMEM>>>(bufA, b_tree, bufB);

    cls_kernel<<<512, 256>>>(bufB, W_cls, b_cls, out);
}

// round 9
// speedup vs baseline: 4.0200x; 1.0109x over previous
#include <cuda_runtime.h>
#include <cstdint>

// ---------------- buffers ----------------
__device__ float g_bufA[131072ull * 128ull];   // l1 then l5
__device__ float g_bufB[32768ull * 128ull];    // l3 then l6
__device__ float g_Wtf[128 * 256];             // W_tree tf32 bits
__device__ float g_embtf[100000ull * 128ull];  // embedding tf32 bits
__device__ int   g_tok_is64;

// ---------------- prep ----------------
__global__ void prep_tok(const int* __restrict__ tok32) {
    __shared__ int bad;
    if (threadIdx.x == 0) bad = 0;
    __syncthreads();
    if (threadIdx.x < 128 && tok32[2 * threadIdx.x + 1] != 0) atomicAdd(&bad, 1);
    __syncthreads();
    if (threadIdx.x == 0) g_tok_is64 = (bad == 0);
}

__device__ __forceinline__ uint32_t f2tf(float x) {
    uint32_t r;
    asm("cvt.rna.tf32.f32 %0, %1;" : "=r"(r) : "f"(x));
    return r;
}

__global__ void prep_w(const float* __restrict__ W) {
    int i = blockIdx.x * 256 + threadIdx.x;
    if (i < 128 * 256) g_Wtf[i] = __uint_as_float(f2tf(W[i]));
}

__global__ void prep_emb(const float* __restrict__ emb) {
    const float4* src = (const float4*)emb;
    float4* dst = (float4*)g_embtf;
    const int n4 = 100000 * 32;
    for (int i = blockIdx.x * blockDim.x + threadIdx.x; i < n4;
         i += gridDim.x * blockDim.x) {
        float4 v = src[i];
        float4 o;
        o.x = __uint_as_float(f2tf(v.x));
        o.y = __uint_as_float(f2tf(v.y));
        o.z = __uint_as_float(f2tf(v.z));
        o.w = __uint_as_float(f2tf(v.w));
        dst[i] = o;
    }
}

// ---------------- helpers ----------------
__device__ __forceinline__ float tanh_fast(float x) {
    float xc = fminf(fmaxf(x, -20.f), 20.f);
    float t = __expf(2.f * xc);
    return __fdividef(t - 1.f, t + 1.f);
}

__device__ __forceinline__ void cp16(uint32_t dst, const void* src) {
    asm volatile("cp.async.cg.shared.global [%0], [%1], 16;" :: "r"(dst), "l"(src));
}

__device__ __forceinline__ void ldsm4(uint32_t addr, uint32_t* r) {
    asm volatile("ldmatrix.sync.aligned.m8n8.x4.shared.b16 {%0,%1,%2,%3}, [%4];"
                 : "=r"(r[0]), "=r"(r[1]), "=r"(r[2]), "=r"(r[3]) : "r"(addr));
}

__device__ __forceinline__ void mma_tf32(float* d, const uint32_t* a,
                                         uint32_t b0, uint32_t b1) {
    asm volatile(
        "mma.sync.aligned.m16n8k8.row.col.f32.tf32.tf32.f32 "
        "{%0,%1,%2,%3},{%4,%5,%6,%7},{%8,%9},{%0,%1,%2,%3};"
        : "+f"(d[0]), "+f"(d[1]), "+f"(d[2]), "+f"(d[3])
        : "r"(a[0]), "r"(a[1]), "r"(a[2]), "r"(a[3]), "r"(b0), "r"(b1));
}

__device__ __forceinline__ void sts64(uint32_t addr, uint32_t v0, uint32_t v1) {
    asm volatile("st.shared.v2.b32 [%0], {%1,%2};" :: "r"(addr), "r"(v0), "r"(v1));
}

// ---------------- fused two-level kernel ----------------
// 256 threads / 8 warps.
// Phase 1: 256 rows level-l = tanh(A1[256,256] @ W^T + b) -> smem INT (warp 64x64)
// Phase 2: 128 rows level-(l+1) = tanh(INT[128,256] @ W^T + b) -> global (warp 32x64)
#define F_ABASE 0u
#define F_BBASE 65536u
#define F_INT   98304u
#define F_BIAS  229376u
#define F_TOK   229888u
#define F_SMEM  231936u

template <bool GATHER>
__global__ __launch_bounds__(256, 1)
void fused_tc(const float* __restrict__ Asrc, const void* __restrict__ tokens,
              const float* __restrict__ bias, float* __restrict__ out)
{
    extern __shared__ char smem[];
    const uint32_t sb = (uint32_t)__cvta_generic_to_shared(smem);
    float* bias_s = (float*)(smem + F_BIAS);
    int*   tok_s  = (int*)(smem + F_TOK);

    const int tid = threadIdx.x, lane = tid & 31, warp = tid >> 5;
    const int m0p = blockIdx.x * 256;
    const int jj = lane >> 3, rr = lane & 7;
    const int arow = (jj & 1) * 8 + rr, kqa = jj >> 1;
    const int brow = (jj >> 1) * 8 + rr, kqb = jj & 1;
    const int q = lane >> 2, tg = lane & 3;

    if (tid < 128) bias_s[tid] = bias[tid];
    if (GATHER) {
        const int is64 = g_tok_is64;
#pragma unroll
        for (int i = tid; i < 512; i += 256) {
            int j = i >> 1, side = i & 1;
            int pr = m0p + j;
            long long ti = (long long)(pr >> 6) * 128 + 2 * (pr & 63) + side;
            tok_s[i] = is64 ? (int)((const long long*)tokens)[ti]
                            : ((const int*)tokens)[ti];
        }
    }
    __syncthreads();

    // ---- precomputed cp.async source/dest (A: 8 units, B: 4 units per thread) ----
    const float* aptr[8];
    int tkL[8], tkR[8], uof[8];
    uint32_t adst[8];
#pragma unroll
    for (int p = 0; p < 8; ++p) {
        int idx = tid + p * 256;
        int row = idx >> 3, u = idx & 7;
        adst[p] = (uint32_t)(row * 128 + ((u ^ (row & 7)) << 4));
        if (GATHER) {
            tkL[p] = tok_s[2 * row];
            tkR[p] = tok_s[2 * row + 1];
            uof[p] = u * 4;
        } else {
            aptr[p] = Asrc + (long long)(m0p + row) * 256 + u * 4;
        }
    }
    const float* bptr[4];
    uint32_t bdst[4];
#pragma unroll
    for (int p = 0; p < 4; ++p) {
        int idx = tid + p * 256;
        int row = idx >> 3, u = idx & 7;
        bdst[p] = (uint32_t)(row * 128 + ((u ^ (row & 7)) << 4));
        bptr[p] = g_Wtf + row * 256 + u * 4;
    }

    auto issueA1 = [&](int kc) {
        const uint32_t d = sb + F_ABASE + (uint32_t)(kc & 1) * 32768u;
        const int co = (kc & 3) * 32;
#pragma unroll
        for (int p = 0; p < 8; ++p) {
            const float* src;
            if (GATHER) {
                long long tk = (kc >> 2) ? tkR[p] : tkL[p];
                src = g_embtf + tk * 128 + co + uof[p];
            } else {
                src = aptr[p] + kc * 32;
            }
            cp16(d + adst[p], src);
        }
    };
    auto issueB = [&](int kc) {
        const uint32_t d = sb + F_BBASE + (uint32_t)(kc & 1) * 16384u;
#pragma unroll
        for (int p = 0; p < 4; ++p)
            cp16(d + bdst[p], bptr[p] + kc * 32);
    };

    // ---- precomputed ldmatrix offsets ----
    uint32_t koA[4], koB[4];
#pragma unroll
    for (int ks = 0; ks < 4; ++ks) {
        koA[ks] = (uint32_t)(((((ks << 1) | kqa) ^ rr) << 4));
        koB[ks] = (uint32_t)(((((ks << 1) | kqb) ^ rr) << 4));
    }

    // ================= phase 1: warp tile 64x64 =================
    const int wm1 = (warp & 3) * 64, wn1 = (warp >> 2) * 64;
    uint32_t am1[4], bn1[4];
#pragma unroll
    for (int i = 0; i < 4; ++i) {
        am1[i] = (uint32_t)((wm1 + i * 16 + arow) * 128);
        bn1[i] = (uint32_t)((wn1 + i * 16 + brow) * 128);
    }

    float acc[4][8][4];
#pragma unroll
    for (int a = 0; a < 4; ++a)
#pragma unroll
        for (int b = 0; b < 8; ++b)
#pragma unroll
            for (int c = 0; c < 4; ++c) acc[a][b][c] = 0.f;

    issueA1(0); issueB(0); asm volatile("cp.async.commit_group;");
    issueA1(1); issueB(1); asm volatile("cp.async.commit_group;");

    for (int kc = 0; kc < 8; ++kc) {
        if (kc < 7) asm volatile("cp.async.wait_group 1;");
        else        asm volatile("cp.async.wait_group 0;");
        __syncthreads();
        const uint32_t Ab = sb + F_ABASE + (uint32_t)(kc & 1) * 32768u;
        const uint32_t Bb = sb + F_BBASE + (uint32_t)(kc & 1) * 16384u;
#pragma unroll
        for (int ks = 0; ks < 4; ++ks) {
            uint32_t af[4][4], bf[4][4];
#pragma unroll
            for (int mi = 0; mi < 4; ++mi) ldsm4(Ab + am1[mi] + koA[ks], af[mi]);
#pragma unroll
            for (int nt = 0; nt < 4; ++nt) ldsm4(Bb + bn1[nt] + koB[ks], bf[nt]);
#pragma unroll
            for (int ni = 0; ni < 8; ++ni) {
                uint32_t b0 = bf[ni >> 1][(ni & 1) * 2];
                uint32_t b1 = bf[ni >> 1][(ni & 1) * 2 + 1];
#pragma unroll
                for (int mi = 0; mi < 4; ++mi) mma_tf32(acc[mi][ni], af[mi], b0, b1);
            }
        }
        __syncthreads();
        if (kc < 6) { issueA1(kc + 2); issueB(kc + 2); asm volatile("cp.async.commit_group;"); }
    }

    // phase-1 epilogue -> INT (phase-2 chunk-swizzled layout)
    auto emit1 = [&](int r, int c, float v0, float v1) {
        uint32_t t0 = f2tf(tanh_fast(v0 + bias_s[c]));
        uint32_t t1 = f2tf(tanh_fast(v1 + bias_s[c + 1]));
        int R = r >> 1, c2 = ((r & 1) << 7) + c;
        int ch = c2 >> 5, k = c2 & 31;
        uint32_t off = sb + F_INT + (uint32_t)(ch * 16384 + R * 128 +
                       (((k >> 2) ^ (R & 7)) << 4) + ((k & 3) << 2));
        sts64(off, t0, t1);
    };
#pragma unroll
    for (int mi = 0; mi < 4; ++mi)
#pragma unroll
        for (int ni = 0; ni < 8; ++ni) {
            int col = wn1 + ni * 8 + 2 * tg;
            int r0 = wm1 + mi * 16 + q;
            emit1(r0,     col, acc[mi][ni][0], acc[mi][ni][1]);
            emit1(r0 + 8, col, acc[mi][ni][2], acc[mi][ni][3]);
        }
    __syncthreads();

    // ================= phase 2: warp tile 32x64, A = INT =================
    const int wm2 = (warp & 3) * 32, wn2 = (warp >> 2) * 64;
    uint32_t am2[2], bn2[4];
#pragma unroll
    for (int i = 0; i < 2; ++i) am2[i] = (uint32_t)((wm2 + i * 16 + arow) * 128);
#pragma unroll
    for (int i = 0; i < 4; ++i) bn2[i] = (uint32_t)((wn2 + i * 16 + brow) * 128);

    float ac2[2][8][4];
#pragma unroll
    for (int a = 0; a < 2; ++a)
#pragma unroll
        for (int b = 0; b < 8; ++b)
#pragma unroll
            for (int c = 0; c < 4; ++c) ac2[a][b][c] = 0.f;

    issueB(0); asm volatile("cp.async.commit_group;");
    issueB(1); asm volatile("cp.async.commit_group;");

    for (int kc = 0; kc < 8; ++kc) {
        if (kc < 7) asm volatile("cp.async.wait_group 1;");
        else        asm volatile("cp.async.wait_group 0;");
        __syncthreads();
        const uint32_t Ab = sb + F_INT + (uint32_t)kc * 16384u;
        const uint32_t Bb = sb + F_BBASE + (uint32_t)(kc & 1) * 16384u;
#pragma unroll
        for (int ks = 0; ks < 4; ++ks) {
            uint32_t af[2][4], bf[4][4];
#pragma unroll
            for (int mi = 0; mi < 2; ++mi) ldsm4(Ab + am2[mi] + koA[ks], af[mi]);
#pragma unroll
            for (int nt = 0; nt < 4; ++nt) ldsm4(Bb + bn2[nt] + koB[ks], bf[nt]);
#pragma unroll
            for (int ni = 0; ni < 8; ++ni) {
                uint32_t b0 = bf[ni >> 1][(ni & 1) * 2];
                uint32_t b1 = bf[ni >> 1][(ni & 1) * 2 + 1];
#pragma unroll
                for (int mi = 0; mi < 2; ++mi) mma_tf32(ac2[mi][ni], af[mi], b0, b1);
            }
        }
        __syncthreads();
        if (kc < 6) { issueB(kc + 2); asm volatile("cp.async.commit_group;"); }
    }

    // phase-2 epilogue -> global tf32 bits
    const int cb = blockIdx.x * 128;
#pragma unroll
    for (int mi = 0; mi < 2; ++mi)
#pragma unroll
        for (int ni = 0; ni < 8; ++ni) {
            int col = wn2 + ni * 8 + 2 * tg;
            float bv0 = bias_s[col], bv1 = bias_s[col + 1];
            int r0 = cb + wm2 + mi * 16 + q;
            float2 v0, v1;
            v0.x = __uint_as_float(f2tf(tanh_fast(ac2[mi][ni][0] + bv0)));
            v0.y = __uint_as_float(f2tf(tanh_fast(ac2[mi][ni][1] + bv1)));
            v1.x = __uint_as_float(f2tf(tanh_fast(ac2[mi][ni][2] + bv0)));
            v1.y = __uint_as_float(f2tf(tanh_fast(ac2[mi][ni][3] + bv1)));
            *(float2*)(out + (long long)r0 * 128 + col)       = v0;
            *(float2*)(out + (long long)(r0 + 8) * 128 + col) = v1;
        }
}

// ---------------- single-level kernel (level 6, fp32 out) ----------------
#define S_ABASE 0u
#define S_BBASE 32768u
#define S_BIAS  65536u
#define S_SMEM  66048u

__global__ __launch_bounds__(256, 1)
void single_tc(const float* __restrict__ Asrc, const float* __restrict__ bias,
               float* __restrict__ out)
{
    extern __shared__ char smem[];
    const uint32_t sb = (uint32_t)__cvta_generic_to_shared(smem);
    float* bias_s = (float*)(smem + S_BIAS);

    const int tid = threadIdx.x, lane = tid & 31, warp = tid >> 5;
    const int m0 = blockIdx.x * 128;
    const int jj = lane >> 3, rr = lane & 7;
    const int arow = (jj & 1) * 8 + rr, kqa = jj >> 1;
    const int brow = (jj >> 1) * 8 + rr, kqb = jj & 1;
    const int q = lane >> 2, tg = lane & 3;

    if (tid < 128) bias_s[tid] = bias[tid];
    __syncthreads();

    const float* aptr[4];
    const float* bptr[4];
    uint32_t dstp[4];
#pragma unroll
    for (int p = 0; p < 4; ++p) {
        int idx = tid + p * 256;
        int row = idx >> 3, u = idx & 7;
        dstp[p] = (uint32_t)(row * 128 + ((u ^ (row & 7)) << 4));
        aptr[p] = Asrc + (long long)(m0 + row) * 256 + u * 4;
        bptr[p] = g_Wtf + row * 256 + u * 4;
    }
    auto issue = [&](int kc) {
        const uint32_t da = sb + S_ABASE + (uint32_t)(kc & 1) * 16384u;
        const uint32_t db = sb + S_BBASE + (uint32_t)(kc & 1) * 16384u;
#pragma unroll
        for (int p = 0; p < 4; ++p) {
            cp16(da + dstp[p], aptr[p] + kc * 32);
            cp16(db + dstp[p], bptr[p] + kc * 32);
        }
        asm volatile("cp.async.commit_group;");
    };

    uint32_t koA[4], koB[4];
#pragma unroll
    for (int ks = 0; ks < 4; ++ks) {
        koA[ks] = (uint32_t)(((((ks << 1) | kqa) ^ rr) << 4));
        koB[ks] = (uint32_t)(((((ks << 1) | kqb) ^ rr) << 4));
    }
    const int wm = (warp & 3) * 32, wn = (warp >> 2) * 64;
    uint32_t am[2], bn[4];
#pragma unroll
    for (int i = 0; i < 2; ++i) am[i] = (uint32_t)((wm + i * 16 + arow) * 128);
#pragma unroll
    for (int i = 0; i < 4; ++i) bn[i] = (uint32_t)((wn + i * 16 + brow) * 128);

    float acc[2][8][4];
#pragma unroll
    for (int a = 0; a < 2; ++a)
#pragma unroll
        for (int b = 0; b < 8; ++b)
#pragma unroll
            for (int c = 0; c < 4; ++c) acc[a][b][c] = 0.f;

    issue(0); issue(1);
    for (int kc = 0; kc < 8; ++kc) {
        if (kc < 7) asm volatile("cp.async.wait_group 1;");
        else        asm volatile("cp.async.wait_group 0;");
        __syncthreads();
        const uint32_t Ab = sb + S_ABASE + (uint32_t)(kc & 1) * 16384u;
        const uint32_t Bb = sb + S_BBASE + (uint32_t)(kc & 1) * 16384u;
#pragma unroll
        for (int ks = 0; ks < 4; ++ks) {
            uint32_t af[2][4], bf[4][4];
#pragma unroll
            for (int mi = 0; mi < 2; ++mi) ldsm4(Ab + am[mi] + koA[ks], af[mi]);
#pragma unroll
            for (int nt = 0; nt < 4; ++nt) ldsm4(Bb + bn[nt] + koB[ks], bf[nt]);
#pragma unroll
            for (int ni = 0; ni < 8; ++ni) {
                uint32_t b0 = bf[ni >> 1][(ni & 1) * 2];
                uint32_t b1 = bf[ni >> 1][(ni & 1) * 2 + 1];
#pragma unroll
                for (int mi = 0; mi < 2; ++mi) mma_tf32(acc[mi][ni], af[mi], b0, b1);
            }
        }
        __syncthreads();
        if (kc < 6) issue(kc + 2);
    }

#pragma unroll
    for (int mi = 0; mi < 2; ++mi)
#pragma unroll
        for (int ni = 0; ni < 8; ++ni) {
            int col = wn + ni * 8 + 2 * tg;
            float bv0 = bias_s[col], bv1 = bias_s[col + 1];
            int r0 = m0 + wm + mi * 16 + q;
            float2 v0, v1;
            v0.x = tanh_fast(acc[mi][ni][0] + bv0);
            v0.y = tanh_fast(acc[mi][ni][1] + bv1);
            v1.x = tanh_fast(acc[mi][ni][2] + bv0);
            v1.y = tanh_fast(acc[mi][ni][3] + bv1);
            *(float2*)(out + (long long)r0 * 128 + col)       = v0;
            *(float2*)(out + (long long)(r0 + 8) * 128 + col) = v1;
        }
}

// ---------------- classifier ----------------
__global__ void cls_kernel(const float* __restrict__ reps,
                           const float* __restrict__ Wc,
                           const float* __restrict__ bc,
                           float* __restrict__ out)
{
    int warp = threadIdx.x >> 5, lane = threadIdx.x & 31;
    int row = blockIdx.x * 8 + warp;
    float4 rv = ((const float4*)(reps + (long long)row * 128))[lane];
    float s[3];
#pragma unroll
    for (int o = 0; o < 3; ++o) {
        float4 wv = __ldg((const float4*)(Wc + o * 128) + lane);
        s[o] = rv.x * wv.x + rv.y * wv.y + rv.z * wv.z + rv.w * wv.w;
    }
#pragma unroll
    for (int off = 16; off; off >>= 1)
#pragma unroll
        for (int o = 0; o < 3; ++o) s[o] += __shfl_xor_sync(~0u, s[o], off);
    if (lane < 3) out[row * 3 + lane] = s[lane] + __ldg(&bc[lane]);
}

// ---------------- launch ----------------
extern "C" void kernel_launch(void* const* d_in, const int* in_sizes, int n_in,
                              void* d_out, int out_size)
{
    const void*  tokens = d_in[0];
    const float* emb    = (const float*)d_in[1];
    const float* W_tree = (const float*)d_in[2];
    const float* b_tree = (const float*)d_in[3];
    const float* W_cls  = (const float*)d_in[4];
    const float* b_cls  = (const float*)d_in[5];
    float* out = (float*)d_out;

    float *bufA, *bufB;
    cudaGetSymbolAddress((void**)&bufA, g_bufA);
    cudaGetSymbolAddress((void**)&bufB, g_bufB);

    cudaFuncSetAttribute(fused_tc<true>,
                         cudaFuncAttributeMaxDynamicSharedMemorySize, F_SMEM);
    cudaFuncSetAttribute(fused_tc<false>,
                         cudaFuncAttributeMaxDynamicSharedMemorySize, F_SMEM);
    cudaFuncSetAttribute(single_tc,
                         cudaFuncAttributeMaxDynamicSharedMemorySize, S_SMEM);

    prep_tok<<<1, 128>>>((const int*)tokens);
    prep_w<<<128, 256>>>(W_tree);
    prep_emb<<<4096, 512>>>(emb);

    // F0: levels 0+1 (gather fused) -> bufA holds l1 [131072,128]
    fused_tc<true><<<1024, 256, F_SMEM>>>(nullptr, tokens, b_tree, bufA);
    // F1: levels 2+3 -> bufB holds l3 [32768,128]
    fused_tc<false><<<256, 256, F_SMEM>>>(bufA, nullptr, b_tree, bufB);
    // F2: levels 4+5 -> bufA holds l5 [8192,128]
    fused_tc<false><<<64, 256, F_SMEM>>>(bufB, nullptr, b_tree, bufA);
    // level 6 -> bufB holds roots [4096,128] fp32
    single_tc<<<32, 256, S_SMEM>>>(bufA, b_tree, bufB);

    cls_kernel<<<512, 256>>>(bufB, W_cls, b_cls, out);
}

// round 10
// speedup vs baseline: 7.7801x; 1.9353x over previous
#include <cuda_runtime.h>
#include <cuda_fp16.h>
#include <cstdint>

// ---------------- buffers ----------------
__device__ __half g_l1[131072ull * 128ull];   // l1, later l5
__device__ __half g_l3[32768ull * 128ull];    // l3
__device__ float  g_root[4096ull * 128ull];   // l6 (fp32 for classifier)
__device__ __half g_Wh[128 * 256];            // W_tree fp16
__device__ __half g_embh[100000ull * 128ull]; // embedding fp16
__device__ int    g_tok_is64;

// ---------------- prep ----------------
__global__ void prep_tok(const int* __restrict__ tok32) {
    __shared__ int bad;
    if (threadIdx.x == 0) bad = 0;
    __syncthreads();
    if (threadIdx.x < 128 && tok32[2 * threadIdx.x + 1] != 0) atomicAdd(&bad, 1);
    __syncthreads();
    if (threadIdx.x == 0) g_tok_is64 = (bad == 0);
}

__global__ void prep_w(const float* __restrict__ W) {
    int i = blockIdx.x * 256 + threadIdx.x;
    if (i < 128 * 256) g_Wh[i] = __float2half_rn(W[i]);
}

__global__ void prep_emb(const float* __restrict__ emb) {
    const float4* src = (const float4*)emb;
    uint2* dst = (uint2*)g_embh;
    const int n4 = 100000 * 32;
    for (int i = blockIdx.x * blockDim.x + threadIdx.x; i < n4;
         i += gridDim.x * blockDim.x) {
        float4 v = src[i];
        __half2 h0 = __floats2half2_rn(v.x, v.y);
        __half2 h1 = __floats2half2_rn(v.z, v.w);
        uint2 o;
        o.x = *(uint32_t*)&h0;
        o.y = *(uint32_t*)&h1;
        dst[i] = o;
    }
}

// ---------------- helpers ----------------
__device__ __forceinline__ float tanh_fast(float x) {
    float xc = fminf(fmaxf(x, -20.f), 20.f);
    float t = __expf(2.f * xc);
    return __fdividef(t - 1.f, t + 1.f);
}

__device__ __forceinline__ uint32_t packh2(float lo, float hi) {
    __half2 h = __floats2half2_rn(lo, hi);
    return *(uint32_t*)&h;
}

__device__ __forceinline__ void cp16(uint32_t dst, const void* src) {
    asm volatile("cp.async.cg.shared.global [%0], [%1], 16;" :: "r"(dst), "l"(src));
}

__device__ __forceinline__ void ldsm4(uint32_t addr, uint32_t* r) {
    asm volatile("ldmatrix.sync.aligned.m8n8.x4.shared.b16 {%0,%1,%2,%3}, [%4];"
                 : "=r"(r[0]), "=r"(r[1]), "=r"(r[2]), "=r"(r[3]) : "r"(addr));
}

__device__ __forceinline__ void mma_f16(float* d, const uint32_t* a,
                                        uint32_t b0, uint32_t b1) {
    asm volatile(
        "mma.sync.aligned.m16n8k16.row.col.f32.f16.f16.f32 "
        "{%0,%1,%2,%3},{%4,%5,%6,%7},{%8,%9},{%0,%1,%2,%3};"
        : "+f"(d[0]), "+f"(d[1]), "+f"(d[2]), "+f"(d[3])
        : "r"(a[0]), "r"(a[1]), "r"(a[2]), "r"(a[3]), "r"(b0), "r"(b1));
}

__device__ __forceinline__ void sts32(uint32_t addr, uint32_t v) {
    asm volatile("st.shared.b32 [%0], %1;" :: "r"(addr), "r"(v));
}

// ---------------- fused two-level kernel (fp16) ----------------
// 256 thr / 8 warps, 2 CTAs/SM. K-chunk = 64 halves (128B rows, SW128).
// Phase 1: 128 rows lvl-l = tanh(A[128,256]@W^T+b) -> INT (overlaid on A stages)
// Phase 2: 64 rows lvl-(l+1) = tanh(INT[64,256]@W^T+b) -> global fp16
// B (=W, fp16, 64KB = 4 chunks) resident in smem, loaded once.
#define FB_OFF  32768u
#define FBIAS   98304u
#define FTOK    98816u
#define F_SMEM  99840u

template <bool GATHER>
__global__ __launch_bounds__(256, 2)
void fused_h(const __half* __restrict__ Asrc, const void* __restrict__ tokens,
             const float* __restrict__ bias, __half* __restrict__ out)
{
    extern __shared__ char smem[];
    const uint32_t sb = (uint32_t)__cvta_generic_to_shared(smem);
    float* bias_s = (float*)(smem + FBIAS);
    int*   tok_s  = (int*)(smem + FTOK);

    const int tid = threadIdx.x, lane = tid & 31, warp = tid >> 5;
    const int m0p = blockIdx.x * 128;
    const int jj = lane >> 3, rr = lane & 7;
    const int frow = (jj & 1) * 8 + rr;   // ldsm row-in-tile (A and B)
    const int fku  = jj >> 1;             // ldsm k-unit select
    const int q = lane >> 2, tg = lane & 3;

    if (tid < 128) bias_s[tid] = bias[tid];
    if (GATHER) {
        const int is64 = g_tok_is64;
        int r = tid >> 1, side = tid & 1;
        int g = m0p + r;
        long long ti = (long long)(g >> 6) * 128 + 2 * (g & 63) + side;
        tok_s[tid] = is64 ? (int)((const long long*)tokens)[ti]
                          : ((const int*)tokens)[ti];
    }
    __syncthreads();

    // ldsm k offsets per k16-step within a 64-half chunk
    uint32_t ko[4];
#pragma unroll
    for (int ks = 0; ks < 4; ++ks)
        ko[ks] = (uint32_t)((((ks * 2 + fku) ^ rr) << 4));

    // cp.async A: 4 units/thread (128 rows x 8 units)
    uint32_t adst[4];
    const __half* aptr[4];
    int aL[4], aR[4], uo[4];
#pragma unroll
    for (int p = 0; p < 4; ++p) {
        int idx = tid + p * 256;
        int row = idx >> 3, u = idx & 7;
        adst[p] = (uint32_t)(row * 128 + ((u ^ (row & 7)) << 4));
        if (GATHER) { aL[p] = tok_s[2 * row]; aR[p] = tok_s[2 * row + 1]; uo[p] = u * 8; }
        else aptr[p] = Asrc + (long long)(m0p + row) * 256 + u * 8;
    }
    auto issueA = [&](int kc) {
        const uint32_t d = sb + (uint32_t)(kc & 1) * 16384u;
#pragma unroll
        for (int p = 0; p < 4; ++p) {
            const __half* src;
            if (GATHER) {
                long long tk = (kc >> 1) ? aR[p] : aL[p];
                src = g_embh + tk * 128 + (kc & 1) * 64 + uo[p];
            } else src = aptr[p] + kc * 64;
            cp16(d + adst[p], src);
        }
    };

    // B resident: 4 chunks x (128 rows x 8 units) = 16 units/thread
    {
#pragma unroll
        for (int p = 0; p < 16; ++p) {
            int i = tid + p * 256;
            int ch = i >> 10, j = i & 1023;
            int row = j >> 3, u = j & 7;
            cp16(sb + FB_OFF + (uint32_t)ch * 16384u +
                 (uint32_t)(row * 128 + ((u ^ (row & 7)) << 4)),
                 g_Wh + row * 256 + ch * 64 + u * 8);
        }
        issueA(0); asm volatile("cp.async.commit_group;");
        issueA(1); asm volatile("cp.async.commit_group;");
    }

    // ---- phase 1: warp tile 32x64 ----
    const int wm1 = (warp & 3) * 32, wn1 = (warp >> 2) * 64;
    uint32_t am1[2], bn1[4];
#pragma unroll
    for (int i = 0; i < 2; ++i) am1[i] = (uint32_t)((wm1 + i * 16 + frow) * 128);
#pragma unroll
    for (int i = 0; i < 4; ++i) bn1[i] = (uint32_t)((wn1 + i * 16 + frow) * 128);

    float acc[2][8][4];
#pragma unroll
    for (int a = 0; a < 2; ++a)
#pragma unroll
        for (int b = 0; b < 8; ++b)
#pragma unroll
            for (int c = 0; c < 4; ++c) acc[a][b][c] = 0.f;

    for (int kc = 0; kc < 4; ++kc) {
        if (kc < 3) asm volatile("cp.async.wait_group 1;");
        else        asm volatile("cp.async.wait_group 0;");
        __syncthreads();
        const uint32_t Ab = sb + (uint32_t)(kc & 1) * 16384u;
        const uint32_t Bb = sb + FB_OFF + (uint32_t)kc * 16384u;
#pragma unroll
        for (int ks = 0; ks < 4; ++ks) {
            uint32_t af[2][4], bf[4][4];
#pragma unroll
            for (int mi = 0; mi < 2; ++mi) ldsm4(Ab + am1[mi] + ko[ks], af[mi]);
#pragma unroll
            for (int nt = 0; nt < 4; ++nt) ldsm4(Bb + bn1[nt] + ko[ks], bf[nt]);
#pragma unroll
            for (int ni = 0; ni < 8; ++ni) {
                uint32_t b0 = bf[ni >> 1][ni & 1];
                uint32_t b1 = bf[ni >> 1][2 + (ni & 1)];
#pragma unroll
                for (int mi = 0; mi < 2; ++mi) mma_f16(acc[mi][ni], af[mi], b0, b1);
            }
        }
        __syncthreads();
        if (kc < 2) { issueA(kc + 2); asm volatile("cp.async.commit_group;"); }
    }

    // phase-1 epilogue -> INT (A region, phase-2 chunk layout)
    auto emit1 = [&](int r, int c, float v0, float v1) {
        uint32_t h2 = packh2(tanh_fast(v0 + bias_s[c]), tanh_fast(v1 + bias_s[c + 1]));
        int R = r >> 1, c2 = ((r & 1) << 7) + c;
        int ch = c2 >> 6, kk = c2 & 63;
        sts32(sb + (uint32_t)(ch * 8192 + R * 128 +
              (((kk >> 3) ^ (R & 7)) << 4) + ((kk & 7) << 1)), h2);
    };
#pragma unroll
    for (int mi = 0; mi < 2; ++mi)
#pragma unroll
        for (int ni = 0; ni < 8; ++ni) {
            int col = wn1 + ni * 8 + 2 * tg;
            int r0 = wm1 + mi * 16 + q;
            emit1(r0,     col, acc[mi][ni][0], acc[mi][ni][1]);
            emit1(r0 + 8, col, acc[mi][ni][2], acc[mi][ni][3]);
        }
    __syncthreads();

    // ---- phase 2: warp tile 16x64, all data resident ----
    const int wm2 = (warp & 3) * 16, wn2 = (warp >> 2) * 64;
    const uint32_t am2 = (uint32_t)((wm2 + frow) * 128);
    uint32_t bn2[4];
#pragma unroll
    for (int i = 0; i < 4; ++i) bn2[i] = (uint32_t)((wn2 + i * 16 + frow) * 128);

    float ac2[8][4];
#pragma unroll
    for (int b = 0; b < 8; ++b)
#pragma unroll
        for (int c = 0; c < 4; ++c) ac2[b][c] = 0.f;

#pragma unroll
    for (int kc = 0; kc < 4; ++kc) {
        const uint32_t Ab = sb + (uint32_t)kc * 8192u;
        const uint32_t Bb = sb + FB_OFF + (uint32_t)kc * 16384u;
#pragma unroll
        for (int ks = 0; ks < 4; ++ks) {
            uint32_t af[4], bf[4][4];
            ldsm4(Ab + am2 + ko[ks], af);
#pragma unroll
            for (int nt = 0; nt < 4; ++nt) ldsm4(Bb + bn2[nt] + ko[ks], bf[nt]);
#pragma unroll
            for (int ni = 0; ni < 8; ++ni)
                mma_f16(ac2[ni], af, bf[ni >> 1][ni & 1], bf[ni >> 1][2 + (ni & 1)]);
        }
    }

    // phase-2 epilogue -> global fp16
    const int cb = blockIdx.x * 64;
#pragma unroll
    for (int ni = 0; ni < 8; ++ni) {
        int col = wn2 + ni * 8 + 2 * tg;
        float bv0 = bias_s[col], bv1 = bias_s[col + 1];
        int r0 = cb + wm2 + q;
        *(uint32_t*)(out + (long long)r0 * 128 + col) =
            packh2(tanh_fast(ac2[ni][0] + bv0), tanh_fast(ac2[ni][1] + bv1));
        *(uint32_t*)(out + (long long)(r0 + 8) * 128 + col) =
            packh2(tanh_fast(ac2[ni][2] + bv0), tanh_fast(ac2[ni][3] + bv1));
    }
}

// ---------------- single-level kernel (level 6, fp32 out) ----------------
__global__ __launch_bounds__(256, 2)
void single_h(const __half* __restrict__ Asrc, const float* __restrict__ bias,
              float* __restrict__ out)
{
    extern __shared__ char smem[];
    const uint32_t sb = (uint32_t)__cvta_generic_to_shared(smem);
    float* bias_s = (float*)(smem + FBIAS);

    const int tid = threadIdx.x, lane = tid & 31, warp = tid >> 5;
    const int m0 = blockIdx.x * 128;
    const int jj = lane >> 3, rr = lane & 7;
    const int frow = (jj & 1) * 8 + rr;
    const int fku  = jj >> 1;
    const int q = lane >> 2, tg = lane & 3;

    if (tid < 128) bias_s[tid] = bias[tid];
    __syncthreads();

    uint32_t ko[4];
#pragma unroll
    for (int ks = 0; ks < 4; ++ks)
        ko[ks] = (uint32_t)((((ks * 2 + fku) ^ rr) << 4));

    uint32_t adst[4];
    const __half* aptr[4];
#pragma unroll
    for (int p = 0; p < 4; ++p) {
        int idx = tid + p * 256;
        int row = idx >> 3, u = idx & 7;
        adst[p] = (uint32_t)(row * 128 + ((u ^ (row & 7)) << 4));
        aptr[p] = Asrc + (long long)(m0 + row) * 256 + u * 8;
    }
    auto issueA = [&](int kc) {
        const uint32_t d = sb + (uint32_t)(kc & 1) * 16384u;
#pragma unroll
        for (int p = 0; p < 4; ++p) cp16(d + adst[p], aptr[p] + kc * 64);
    };
    {
#pragma unroll
        for (int p = 0; p < 16; ++p) {
            int i = tid + p * 256;
            int ch = i >> 10, j = i & 1023;
            int row = j >> 3, u = j & 7;
            cp16(sb + FB_OFF + (uint32_t)ch * 16384u +
                 (uint32_t)(row * 128 + ((u ^ (row & 7)) << 4)),
                 g_Wh + row * 256 + ch * 64 + u * 8);
        }
        issueA(0); asm volatile("cp.async.commit_group;");
        issueA(1); asm volatile("cp.async.commit_group;");
    }

    const int wm = (warp & 3) * 32, wn = (warp >> 2) * 64;
    uint32_t am[2], bn[4];
#pragma unroll
    for (int i = 0; i < 2; ++i) am[i] = (uint32_t)((wm + i * 16 + frow) * 128);
#pragma unroll
    for (int i = 0; i < 4; ++i) bn[i] = (uint32_t)((wn + i * 16 + frow) * 128);

    float acc[2][8][4];
#pragma unroll
    for (int a = 0; a < 2; ++a)
#pragma unroll
        for (int b = 0; b < 8; ++b)
#pragma unroll
            for (int c = 0; c < 4; ++c) acc[a][b][c] = 0.f;

    for (int kc = 0; kc < 4; ++kc) {
        if (kc < 3) asm volatile("cp.async.wait_group 1;");
        else        asm volatile("cp.async.wait_group 0;");
        __syncthreads();
        const uint32_t Ab = sb + (uint32_t)(kc & 1) * 16384u;
        const uint32_t Bb = sb + FB_OFF + (uint32_t)kc * 16384u;
#pragma unroll
        for (int ks = 0; ks < 4; ++ks) {
            uint32_t af[2][4], bf[4][4];
#pragma unroll
            for (int mi = 0; mi < 2; ++mi) ldsm4(Ab + am[mi] + ko[ks], af[mi]);
#pragma unroll
            for (int nt = 0; nt < 4; ++nt) ldsm4(Bb + bn[nt] + ko[ks], bf[nt]);
#pragma unroll
            for (int ni = 0; ni < 8; ++ni) {
                uint32_t b0 = bf[ni >> 1][ni & 1];
                uint32_t b1 = bf[ni >> 1][2 + (ni & 1)];
#pragma unroll
                for (int mi = 0; mi < 2; ++mi) mma_f16(acc[mi][ni], af[mi], b0, b1);
            }
        }
        __syncthreads();
        if (kc < 2) { issueA(kc + 2); asm volatile("cp.async.commit_group;"); }
    }

#pragma unroll
    for (int mi = 0; mi < 2; ++mi)
#pragma unroll
        for (int ni = 0; ni < 8; ++ni) {
            int col = wn + ni * 8 + 2 * tg;
            float bv0 = bias_s[col], bv1 = bias_s[col + 1];
            int r0 = m0 + wm + mi * 16 + q;
            float2 v0, v1;
            v0.x = tanh_fast(acc[mi][ni][0] + bv0);
            v0.y = tanh_fast(acc[mi][ni][1] + bv1);
            v1.x = tanh_fast(acc[mi][ni][2] + bv0);
            v1.y = tanh_fast(acc[mi][ni][3] + bv1);
            *(float2*)(out + (long long)r0 * 128 + col)       = v0;
            *(float2*)(out + (long long)(r0 + 8) * 128 + col) = v1;
        }
}

// ---------------- classifier ----------------
__global__ void cls_kernel(const float* __restrict__ reps,
                           const float* __restrict__ Wc,
                           const float* __restrict__ bc,
                           float* __restrict__ out)
{
    int warp = threadIdx.x >> 5, lane = threadIdx.x & 31;
    int row = blockIdx.x * 8 + warp;
    float4 rv = ((const float4*)(reps + (long long)row * 128))[lane];
    float s[3];
#pragma unroll
    for (int o = 0; o < 3; ++o) {
        float4 wv = __ldg((const float4*)(Wc + o * 128) + lane);
        s[o] = rv.x * wv.x + rv.y * wv.y + rv.z * wv.z + rv.w * wv.w;
    }
#pragma unroll
    for (int off = 16; off; off >>= 1)
#pragma unroll
        for (int o = 0; o < 3; ++o) s[o] += __shfl_xor_sync(~0u, s[o], off);
    if (lane < 3) out[row * 3 + lane] = s[lane] + __ldg(&bc[lane]);
}

// ---------------- launch ----------------
extern "C" void kernel_launch(void* const* d_in, const int* in_sizes, int n_in,
                              void* d_out, int out_size)
{
    const void*  tokens = d_in[0];
    const float* emb    = (const float*)d_in[1];
    const float* W_tree = (const float*)d_in[2];
    const float* b_tree = (const float*)d_in[3];
    const float* W_cls  = (const float*)d_in[4];
    const float* b_cls  = (const float*)d_in[5];
    float* out = (float*)d_out;

    __half *l1, *l3;
    float* root;
    cudaGetSymbolAddress((void**)&l1, g_l1);
    cudaGetSymbolAddress((void**)&l3, g_l3);
    cudaGetSymbolAddress((void**)&root, g_root);

    cudaFuncSetAttribute(fused_h<true>,
                         cudaFuncAttributeMaxDynamicSharedMemorySize, F_SMEM);
    cudaFuncSetAttribute(fused_h<false>,
                         cudaFuncAttributeMaxDynamicSharedMemorySize, F_SMEM);
    cudaFuncSetAttribute(single_h,
                         cudaFuncAttributeMaxDynamicSharedMemorySize, F_SMEM);

    prep_tok<<<1, 128>>>((const int*)tokens);
    prep_w<<<128, 256>>>(W_tree);
    prep_emb<<<2048, 256>>>(emb);

    // F0: levels 0+1 (gather) -> l1 [131072,128] fp16
    fused_h<true><<<2048, 256, F_SMEM>>>(nullptr, tokens, b_tree, l1);
    // F1: levels 2+3: l1 as [65536,256] -> l3 [32768,128]
    fused_h<false><<<512, 256, F_SMEM>>>(l1, nullptr, b_tree, l3);
    // F2: levels 4+5: l3 as [16384,256] -> l5 [8192,128] (into l1 buffer)
    fused_h<false><<<128, 256, F_SMEM>>>(l3, nullptr, b_tree, l1);
    // level 6: l5 as [4096,256] -> roots [4096,128] fp32
    single_h<<<32, 256, F_SMEM>>>(l1, b_tree, root);

    cls_kernel<<<512, 256>>>(root, W_cls, b_cls, out);
}

// round 11
// speedup vs baseline: 8.2834x; 1.0647x over previous
#include <cuda_runtime.h>
#include <cuda_fp16.h>
#include <cstdint>

// ---------------- buffers ----------------
__device__ __half g_l1[131072ull * 128ull];   // level-1 output
__device__ __half g_l4[16384ull * 128ull];    // level-4 output
__device__ __half g_Wh[128 * 256];            // W_tree fp16
__device__ __half g_embh[100000ull * 128ull]; // embedding fp16
__device__ int    g_tok_is64;

// ---------------- prep ----------------
__global__ void prep_wt(const float* __restrict__ W, const int* __restrict__ tok32) {
    int i = blockIdx.x * 256 + threadIdx.x;
    if (i < 128 * 256) g_Wh[i] = __float2half_rn(W[i]);
    if (blockIdx.x == 0) {
        __shared__ int bad;
        if (threadIdx.x == 0) bad = 0;
        __syncthreads();
        if (threadIdx.x < 128 && tok32[2 * threadIdx.x + 1] != 0) atomicAdd(&bad, 1);
        __syncthreads();
        if (threadIdx.x == 0) g_tok_is64 = (bad == 0);
    }
}

__global__ void prep_emb(const float* __restrict__ emb) {
    const float4* src = (const float4*)emb;
    uint2* dst = (uint2*)g_embh;
    const int n4 = 100000 * 32;
    for (int i = blockIdx.x * blockDim.x + threadIdx.x; i < n4;
         i += gridDim.x * blockDim.x) {
        float4 v = src[i];
        __half2 h0 = __floats2half2_rn(v.x, v.y);
        __half2 h1 = __floats2half2_rn(v.z, v.w);
        uint2 o;
        o.x = *(uint32_t*)&h0;
        o.y = *(uint32_t*)&h1;
        dst[i] = o;
    }
}

// ---------------- helpers ----------------
__device__ __forceinline__ float tanh_fast(float x) {
    float t;
    asm("ex2.approx.f32 %0, %1;" : "=f"(t) : "f"(x * 2.885390082f));
    return __fdividef(t - 1.f, t + 1.f);
}

__device__ __forceinline__ uint32_t packh2(float lo, float hi) {
    __half2 h = __floats2half2_rn(lo, hi);
    return *(uint32_t*)&h;
}

__device__ __forceinline__ void cp16(uint32_t dst, const void* src) {
    asm volatile("cp.async.cg.shared.global [%0], [%1], 16;" :: "r"(dst), "l"(src));
}

__device__ __forceinline__ void ldsm4(uint32_t addr, uint32_t* r) {
    asm volatile("ldmatrix.sync.aligned.m8n8.x4.shared.b16 {%0,%1,%2,%3}, [%4];"
                 : "=r"(r[0]), "=r"(r[1]), "=r"(r[2]), "=r"(r[3]) : "r"(addr));
}

__device__ __forceinline__ void mma_f16(float* d, const uint32_t* a,
                                        uint32_t b0, uint32_t b1) {
    asm volatile(
        "mma.sync.aligned.m16n8k16.row.col.f32.f16.f16.f32 "
        "{%0,%1,%2,%3},{%4,%5,%6,%7},{%8,%9},{%0,%1,%2,%3};"
        : "+f"(d[0]), "+f"(d[1]), "+f"(d[2]), "+f"(d[3])
        : "r"(a[0]), "r"(a[1]), "r"(a[2]), "r"(a[3]), "r"(b0), "r"(b1));
}

__device__ __forceinline__ void sts32(uint32_t addr, uint32_t v) {
    asm volatile("st.shared.b32 [%0], %1;" :: "r"(addr), "r"(v));
}

// smem layout (99840 B, 2 CTAs/SM):
//   [0, 32K)  : A stages (2x16K) / INT1 (4x8K) / INT2 (16K) / roots fp32 (32K, tail)
//   [32K,96K) : B resident, 4 chunks x 16K
//   [96K+2K]  : bias (512B) + tok (1K)
#define FB_OFF  32768u
#define FBIAS   98304u
#define FTOK    98816u
#define F_SMEM  99840u

// PHASES=2: out = level l+1 (64 rows/CTA, fp16)
// PHASES=3: out = level l+2 (32 rows/CTA, fp16)
template <bool GATHER, int PHASES>
__global__ __launch_bounds__(256, 2)
void fused_h(const __half* __restrict__ Asrc, const void* __restrict__ tokens,
             const float* __restrict__ bias, __half* __restrict__ out)
{
    extern __shared__ char smem[];
    const uint32_t sb = (uint32_t)__cvta_generic_to_shared(smem);
    float* bias_s = (float*)(smem + FBIAS);
    int*   tok_s  = (int*)(smem + FTOK);

    const int tid = threadIdx.x, lane = tid & 31, warp = tid >> 5;
    const int m0p = blockIdx.x * 128;
    const int jj = lane >> 3, rr = lane & 7;
    const int frow = (jj & 1) * 8 + rr;
    const int fku  = jj >> 1;
    const int q = lane >> 2, tg = lane & 3;

    if (tid < 128) bias_s[tid] = bias[tid];
    if (GATHER) {
        const int is64 = g_tok_is64;
        int r = tid >> 1, side = tid & 1;
        int g = m0p + r;
        long long ti = (long long)(g >> 6) * 128 + 2 * (g & 63) + side;
        tok_s[tid] = is64 ? (int)((const long long*)tokens)[ti]
                          : ((const int*)tokens)[ti];
    }
    __syncthreads();

    uint32_t ko[4];
#pragma unroll
    for (int ks = 0; ks < 4; ++ks)
        ko[ks] = (uint32_t)((((ks * 2 + fku) ^ rr) << 4));

    // A loads: 4 units/thread
    uint32_t adst[4];
    const __half* aptr[4];
    int aL[4], aR[4], uo[4];
#pragma unroll
    for (int p = 0; p < 4; ++p) {
        int idx = tid + p * 256;
        int row = idx >> 3, u = idx & 7;
        adst[p] = (uint32_t)(row * 128 + ((u ^ (row & 7)) << 4));
        if (GATHER) { aL[p] = tok_s[2 * row]; aR[p] = tok_s[2 * row + 1]; uo[p] = u * 8; }
        else aptr[p] = Asrc + (long long)(m0p + row) * 256 + u * 8;
    }
    auto issueA = [&](int kc) {
        const uint32_t d = sb + (uint32_t)(kc & 1) * 16384u;
#pragma unroll
        for (int p = 0; p < 4; ++p) {
            const __half* src;
            if (GATHER) {
                long long tk = (kc >> 1) ? aR[p] : aL[p];
                src = g_embh + tk * 128 + (kc & 1) * 64 + uo[p];
            } else src = aptr[p] + kc * 64;
            cp16(d + adst[p], src);
        }
    };

    // B loads: 4 units/thread per chunk
    uint32_t bdst[4];
    const __half* bptr[4];
#pragma unroll
    for (int p = 0; p < 4; ++p) {
        int i = tid + p * 256;
        int row = i >> 3, u = i & 7;
        bdst[p] = (uint32_t)(row * 128 + ((u ^ (row & 7)) << 4));
        bptr[p] = g_Wh + row * 256 + u * 8;
    }
    auto issueB = [&](int ch) {
        const uint32_t d = sb + FB_OFF + (uint32_t)ch * 16384u;
#pragma unroll
        for (int p = 0; p < 4; ++p)
            cp16(d + bdst[p], bptr[p] + ch * 64);
    };

    // ramp: G0={B0,A0} G1={B1,A1} G2={B2} G3={B3}
    issueB(0); issueA(0); asm volatile("cp.async.commit_group;");
    issueB(1); issueA(1); asm volatile("cp.async.commit_group;");
    issueB(2); asm volatile("cp.async.commit_group;");
    issueB(3); asm volatile("cp.async.commit_group;");

    // ---- phase 1: warp tile 32x64 ----
    const int wm1 = (warp & 3) * 32, wn1 = (warp >> 2) * 64;
    uint32_t am1[2], bn1[4];
#pragma unroll
    for (int i = 0; i < 2; ++i) am1[i] = (uint32_t)((wm1 + i * 16 + frow) * 128);
#pragma unroll
    for (int i = 0; i < 4; ++i) bn1[i] = (uint32_t)((wn1 + i * 16 + frow) * 128);

    float acc[2][8][4];
#pragma unroll
    for (int a = 0; a < 2; ++a)
#pragma unroll
        for (int b = 0; b < 8; ++b)
#pragma unroll
            for (int c = 0; c < 4; ++c) acc[a][b][c] = 0.f;

    for (int kc = 0; kc < 4; ++kc) {
        if (kc < 2)       asm volatile("cp.async.wait_group 3;");
        else if (kc == 2) asm volatile("cp.async.wait_group 1;");
        else              asm volatile("cp.async.wait_group 0;");
        __syncthreads();
        const uint32_t Ab = sb + (uint32_t)(kc & 1) * 16384u;
        const uint32_t Bb = sb + FB_OFF + (uint32_t)kc * 16384u;
#pragma unroll
        for (int ks = 0; ks < 4; ++ks) {
            uint32_t af[2][4], bf[4][4];
#pragma unroll
            for (int mi = 0; mi < 2; ++mi) ldsm4(Ab + am1[mi] + ko[ks], af[mi]);
#pragma unroll
            for (int nt = 0; nt < 4; ++nt) ldsm4(Bb + bn1[nt] + ko[ks], bf[nt]);
#pragma unroll
            for (int ni = 0; ni < 8; ++ni) {
                uint32_t b0 = bf[ni >> 1][ni & 1];
                uint32_t b1 = bf[ni >> 1][2 + (ni & 1)];
#pragma unroll
                for (int mi = 0; mi < 2; ++mi) mma_f16(acc[mi][ni], af[mi], b0, b1);
            }
        }
        __syncthreads();
        if (kc < 2) { issueA(kc + 2); asm volatile("cp.async.commit_group;"); }
    }

    // phase-1 epilogue -> INT1 ([64,256] chunk layout over A region)
    auto emit1 = [&](int r, int c, float v0, float v1) {
        uint32_t h2 = packh2(tanh_fast(v0 + bias_s[c]), tanh_fast(v1 + bias_s[c + 1]));
        int R = r >> 1, c2 = ((r & 1) << 7) + c;
        int ch = c2 >> 6, kk = c2 & 63;
        sts32(sb + (uint32_t)(ch * 8192 + R * 128 +
              (((kk >> 3) ^ (R & 7)) << 4) + ((kk & 7) << 1)), h2);
    };
#pragma unroll
    for (int mi = 0; mi < 2; ++mi)
#pragma unroll
        for (int ni = 0; ni < 8; ++ni) {
            int col = wn1 + ni * 8 + 2 * tg;
            int r0 = wm1 + mi * 16 + q;
            emit1(r0,     col, acc[mi][ni][0], acc[mi][ni][1]);
            emit1(r0 + 8, col, acc[mi][ni][2], acc[mi][ni][3]);
        }
    __syncthreads();

    // ---- phase 2: warp tile 16x64, all resident ----
    const int wm2 = (warp & 3) * 16, wn2 = (warp >> 2) * 64;
    const uint32_t am2 = (uint32_t)((wm2 + frow) * 128);
    uint32_t bn2[4];
#pragma unroll
    for (int i = 0; i < 4; ++i) bn2[i] = (uint32_t)((wn2 + i * 16 + frow) * 128);

    float ac2[8][4];
#pragma unroll
    for (int b = 0; b < 8; ++b)
#pragma unroll
        for (int c = 0; c < 4; ++c) ac2[b][c] = 0.f;

#pragma unroll
    for (int kc = 0; kc < 4; ++kc) {
        const uint32_t Ab = sb + (uint32_t)kc * 8192u;
        const uint32_t Bb = sb + FB_OFF + (uint32_t)kc * 16384u;
#pragma unroll
        for (int ks = 0; ks < 4; ++ks) {
            uint32_t af[4], bf[4][4];
            ldsm4(Ab + am2 + ko[ks], af);
#pragma unroll
            for (int nt = 0; nt < 4; ++nt) ldsm4(Bb + bn2[nt] + ko[ks], bf[nt]);
#pragma unroll
            for (int ni = 0; ni < 8; ++ni)
                mma_f16(ac2[ni], af, bf[ni >> 1][ni & 1], bf[ni >> 1][2 + (ni & 1)]);
        }
    }

    if (PHASES == 2) {
        // phase-2 epilogue -> global fp16 (64 rows/CTA)
        const int cb = blockIdx.x * 64;
#pragma unroll
        for (int ni = 0; ni < 8; ++ni) {
            int col = wn2 + ni * 8 + 2 * tg;
            float bv0 = bias_s[col], bv1 = bias_s[col + 1];
            int r0 = cb + wm2 + q;
            *(uint32_t*)(out + (long long)r0 * 128 + col) =
                packh2(tanh_fast(ac2[ni][0] + bv0), tanh_fast(ac2[ni][1] + bv1));
            *(uint32_t*)(out + (long long)(r0 + 8) * 128 + col) =
                packh2(tanh_fast(ac2[ni][2] + bv0), tanh_fast(ac2[ni][3] + bv1));
        }
        return;
    }

    // ---- PHASES==3: phase-2 epilogue -> INT2 ([32,256] chunk layout @ offset 0) ----
    __syncthreads();   // all INT1 reads done before overlay
    auto emit2 = [&](int r, int c, float v0, float v1) {
        uint32_t h2 = packh2(tanh_fast(v0 + bias_s[c]), tanh_fast(v1 + bias_s[c + 1]));
        int R = r >> 1, c2 = ((r & 1) << 7) + c;
        int ch = c2 >> 6, kk = c2 & 63;
        sts32(sb + (uint32_t)(ch * 4096 + R * 128 +
              (((kk >> 3) ^ (R & 7)) << 4) + ((kk & 7) << 1)), h2);
    };
#pragma unroll
    for (int ni = 0; ni < 8; ++ni) {
        int col = wn2 + ni * 8 + 2 * tg;
        int r0 = wm2 + q;
        emit2(r0,     col, ac2[ni][0], ac2[ni][1]);
        emit2(r0 + 8, col, ac2[ni][2], ac2[ni][3]);
    }
    __syncthreads();

    // ---- phase 3: warp tile 16x32 over M=32,N=128 ----
    const int wm3 = (warp & 1) * 16, wn3 = (warp >> 1) * 32;
    const uint32_t am3 = (uint32_t)((wm3 + frow) * 128);
    uint32_t bn3[2];
#pragma unroll
    for (int i = 0; i < 2; ++i) bn3[i] = (uint32_t)((wn3 + i * 16 + frow) * 128);

    float ac3[4][4];
#pragma unroll
    for (int b = 0; b < 4; ++b)
#pragma unroll
        for (int c = 0; c < 4; ++c) ac3[b][c] = 0.f;

#pragma unroll
    for (int kc = 0; kc < 4; ++kc) {
        const uint32_t Ab = sb + (uint32_t)kc * 4096u;
        const uint32_t Bb = sb + FB_OFF + (uint32_t)kc * 16384u;
#pragma unroll
        for (int ks = 0; ks < 4; ++ks) {
            uint32_t af[4], bf[2][4];
            ldsm4(Ab + am3 + ko[ks], af);
#pragma unroll
            for (int nt = 0; nt < 2; ++nt) ldsm4(Bb + bn3[nt] + ko[ks], bf[nt]);
#pragma unroll
            for (int ni = 0; ni < 4; ++ni)
                mma_f16(ac3[ni], af, bf[ni >> 1][ni & 1], bf[ni >> 1][2 + (ni & 1)]);
        }
    }

    // phase-3 epilogue -> global fp16 (32 rows/CTA)
    const int cb3 = blockIdx.x * 32;
#pragma unroll
    for (int ni = 0; ni < 4; ++ni) {
        int col = wn3 + ni * 8 + 2 * tg;
        float bv0 = bias_s[col], bv1 = bias_s[col + 1];
        int r0 = cb3 + wm3 + q;
        *(uint32_t*)(out + (long long)r0 * 128 + col) =
            packh2(tanh_fast(ac3[ni][0] + bv0), tanh_fast(ac3[ni][1] + bv1));
        *(uint32_t*)(out + (long long)(r0 + 8) * 128 + col) =
            packh2(tanh_fast(ac3[ni][2] + bv0), tanh_fast(ac3[ni][3] + bv1));
    }
}

// ---------------- tail: l5 + l6 + classifier ----------------
__global__ __launch_bounds__(256, 2)
void tail_h(const __half* __restrict__ Asrc, const float* __restrict__ bias,
            const float* __restrict__ Wc, const float* __restrict__ bc,
            float* __restrict__ out3)
{
    extern __shared__ char smem[];
    const uint32_t sb = (uint32_t)__cvta_generic_to_shared(smem);
    float* bias_s = (float*)(smem + FBIAS);

    const int tid = threadIdx.x, lane = tid & 31, warp = tid >> 5;
    const int m0 = blockIdx.x * 128;
    const int jj = lane >> 3, rr = lane & 7;
    const int frow = (jj & 1) * 8 + rr;
    const int fku  = jj >> 1;
    const int q = lane >> 2, tg = lane & 3;

    if (tid < 128) bias_s[tid] = bias[tid];
    __syncthreads();

    uint32_t ko[4];
#pragma unroll
    for (int ks = 0; ks < 4; ++ks)
        ko[ks] = (uint32_t)((((ks * 2 + fku) ^ rr) << 4));

    uint32_t adst[4];
    const __half* aptr[4];
#pragma unroll
    for (int p = 0; p < 4; ++p) {
        int idx = tid + p * 256;
        int row = idx >> 3, u = idx & 7;
        adst[p] = (uint32_t)(row * 128 + ((u ^ (row & 7)) << 4));
        aptr[p] = Asrc + (long long)(m0 + row) * 256 + u * 8;
    }
    uint32_t bdst[4];
    const __half* bptr[4];
#pragma unroll
    for (int p = 0; p < 4; ++p) {
        int i = tid + p * 256;
        int row = i >> 3, u = i & 7;
        bdst[p] = (uint32_t)(row * 128 + ((u ^ (row & 7)) << 4));
        bptr[p] = g_Wh + row * 256 + u * 8;
    }
    auto issueA = [&](int kc) {
        const uint32_t d = sb + (uint32_t)(kc & 1) * 16384u;
#pragma unroll
        for (int p = 0; p < 4; ++p) cp16(d + adst[p], aptr[p] + kc * 64);
    };
    auto issueB = [&](int ch) {
        const uint32_t d = sb + FB_OFF + (uint32_t)ch * 16384u;
#pragma unroll
        for (int p = 0; p < 4; ++p) cp16(d + bdst[p], bptr[p] + ch * 64);
    };

    issueB(0); issueA(0); asm volatile("cp.async.commit_group;");
    issueB(1); issueA(1); asm volatile("cp.async.commit_group;");
    issueB(2); asm volatile("cp.async.commit_group;");
    issueB(3); asm volatile("cp.async.commit_group;");

    // phase 1 (l5): warp 32x64
    const int wm1 = (warp & 3) * 32, wn1 = (warp >> 2) * 64;
    uint32_t am1[2], bn1[4];
#pragma unroll
    for (int i = 0; i < 2; ++i) am1[i] = (uint32_t)((wm1 + i * 16 + frow) * 128);
#pragma unroll
    for (int i = 0; i < 4; ++i) bn1[i] = (uint32_t)((wn1 + i * 16 + frow) * 128);

    float acc[2][8][4];
#pragma unroll
    for (int a = 0; a < 2; ++a)
#pragma unroll
        for (int b = 0; b < 8; ++b)
#pragma unroll
            for (int c = 0; c < 4; ++c) acc[a][b][c] = 0.f;

    for (int kc = 0; kc < 4; ++kc) {
        if (kc < 2)       asm volatile("cp.async.wait_group 3;");
        else if (kc == 2) asm volatile("cp.async.wait_group 1;");
        else              asm volatile("cp.async.wait_group 0;");
        __syncthreads();
        const uint32_t Ab = sb + (uint32_t)(kc & 1) * 16384u;
        const uint32_t Bb = sb + FB_OFF + (uint32_t)kc * 16384u;
#pragma unroll
        for (int ks = 0; ks < 4; ++ks) {
            uint32_t af[2][4], bf[4][4];
#pragma unroll
            for (int mi = 0; mi < 2; ++mi) ldsm4(Ab + am1[mi] + ko[ks], af[mi]);
#pragma unroll
            for (int nt = 0; nt < 4; ++nt) ldsm4(Bb + bn1[nt] + ko[ks], bf[nt]);
#pragma unroll
            for (int ni = 0; ni < 8; ++ni) {
                uint32_t b0 = bf[ni >> 1][ni & 1];
                uint32_t b1 = bf[ni >> 1][2 + (ni & 1)];
#pragma unroll
                for (int mi = 0; mi < 2; ++mi) mma_f16(acc[mi][ni], af[mi], b0, b1);
            }
        }
        __syncthreads();
        if (kc < 2) { issueA(kc + 2); asm volatile("cp.async.commit_group;"); }
    }

    auto emit1 = [&](int r, int c, float v0, float v1) {
        uint32_t h2 = packh2(tanh_fast(v0 + bias_s[c]), tanh_fast(v1 + bias_s[c + 1]));
        int R = r >> 1, c2 = ((r & 1) << 7) + c;
        int ch = c2 >> 6, kk = c2 & 63;
        sts32(sb + (uint32_t)(ch * 8192 + R * 128 +
              (((kk >> 3) ^ (R & 7)) << 4) + ((kk & 7) << 1)), h2);
    };
#pragma unroll
    for (int mi = 0; mi < 2; ++mi)
#pragma unroll
        for (int ni = 0; ni < 8; ++ni) {
            int col = wn1 + ni * 8 + 2 * tg;
            int r0 = wm1 + mi * 16 + q;
            emit1(r0,     col, acc[mi][ni][0], acc[mi][ni][1]);
            emit1(r0 + 8, col, acc[mi][ni][2], acc[mi][ni][3]);
        }
    __syncthreads();

    // phase 2 (l6): warp 16x64, fp32 roots -> smem
    const int wm2 = (warp & 3) * 16, wn2 = (warp >> 2) * 64;
    const uint32_t am2 = (uint32_t)((wm2 + frow) * 128);
    uint32_t bn2[4];
#pragma unroll
    for (int i = 0; i < 4; ++i) bn2[i] = (uint32_t)((wn2 + i * 16 + frow) * 128);

    float ac2[8][4];
#pragma unroll
    for (int b = 0; b < 8; ++b)
#pragma unroll
        for (int c = 0; c < 4; ++c) ac2[b][c] = 0.f;

#pragma unroll
    for (int kc = 0; kc < 4; ++kc) {
        const uint32_t Ab = sb + (uint32_t)kc * 8192u;
        const uint32_t Bb = sb + FB_OFF + (uint32_t)kc * 16384u;
#pragma unroll
        for (int ks = 0; ks < 4; ++ks) {
            uint32_t af[4], bf[4][4];
            ldsm4(Ab + am2 + ko[ks], af);
#pragma unroll
            for (int nt = 0; nt < 4; ++nt) ldsm4(Bb + bn2[nt] + ko[ks], bf[nt]);
#pragma unroll
            for (int ni = 0; ni < 8; ++ni)
                mma_f16(ac2[ni], af, bf[ni >> 1][ni & 1], bf[ni >> 1][2 + (ni & 1)]);
        }
    }
    __syncthreads();   // INT1 reads done -> overlay roots on A region

    float* roots = (float*)smem;   // [64][128] fp32
#pragma unroll
    for (int ni = 0; ni < 8; ++ni) {
        int col = wn2 + ni * 8 + 2 * tg;
        float bv0 = bias_s[col], bv1 = bias_s[col + 1];
        int r0 = wm2 + q;
        float2 v0, v1;
        v0.x = tanh_fast(ac2[ni][0] + bv0);
        v0.y = tanh_fast(ac2[ni][1] + bv1);
        v1.x = tanh_fast(ac2[ni][2] + bv0);
        v1.y = tanh_fast(ac2[ni][3] + bv1);
        *(float2*)(roots + r0 * 128 + col)       = v0;
        *(float2*)(roots + (r0 + 8) * 128 + col) = v1;
    }
    __syncthreads();

    // classifier: warp w -> rows w*8 .. w*8+7
    const int b0r = blockIdx.x * 64;
#pragma unroll
    for (int j = 0; j < 8; ++j) {
        int r = warp * 8 + j;
        float4 rv = ((const float4*)(roots + r * 128))[lane];
        float s[3];
#pragma unroll
        for (int o = 0; o < 3; ++o) {
            float4 wv = __ldg((const float4*)(Wc + o * 128) + lane);
            s[o] = rv.x * wv.x + rv.y * wv.y + rv.z * wv.z + rv.w * wv.w;
        }
#pragma unroll
        for (int off = 16; off; off >>= 1)
#pragma unroll
            for (int o = 0; o < 3; ++o) s[o] += __shfl_xor_sync(~0u, s[o], off);
        if (lane < 3) out3[(b0r + r) * 3 + lane] = s[lane] + __ldg(&bc[lane]);
    }
}

// ---------------- launch ----------------
extern "C" void kernel_launch(void* const* d_in, const int* in_sizes, int n_in,
                              void* d_out, int out_size)
{
    const void*  tokens = d_in[0];
    const float* emb    = (const float*)d_in[1];
    const float* W_tree = (const float*)d_in[2];
    const float* b_tree = (const float*)d_in[3];
    const float* W_cls  = (const float*)d_in[4];
    const float* b_cls  = (const float*)d_in[5];
    float* out = (float*)d_out;

    __half *l1, *l4;
    cudaGetSymbolAddress((void**)&l1, g_l1);
    cudaGetSymbolAddress((void**)&l4, g_l4);

    cudaFuncSetAttribute(fused_h<true, 2>,
                         cudaFuncAttributeMaxDynamicSharedMemorySize, F_SMEM);
    cudaFuncSetAttribute(fused_h<false, 3>,
                         cudaFuncAttributeMaxDynamicSharedMemorySize, F_SMEM);
    cudaFuncSetAttribute(tail_h,
                         cudaFuncAttributeMaxDynamicSharedMemorySize, F_SMEM);

    prep_wt<<<128, 256>>>(W_tree, (const int*)tokens);
    prep_emb<<<2048, 256>>>(emb);

    // levels 0+1 (gather) -> l1 [131072,128]
    fused_h<true, 2><<<2048, 256, F_SMEM>>>(nullptr, tokens, b_tree, l1);
    // levels 2+3+4: l1 as [65536,256] -> l4 [16384,128]
    fused_h<false, 3><<<512, 256, F_SMEM>>>(l1, nullptr, b_tree, l4);
    // levels 5+6 + classifier: l4 as [8192,256] -> out [4096,3]
    tail_h<<<64, 256, F_SMEM>>>(l4, b_tree, W_cls, b_cls, out);
}